// round 1
// baseline (speedup 1.0000x reference)
#include <cuda_runtime.h>
#include <mma.h>
#include <math.h>

using namespace nvcuda;

// Problem shape (fixed by the reference)
#define BB   2
#define SS   2048
#define DD   1024
#define HH   16
#define DKK  64
#define MM   (BB * SS)   // 4096 rows

// ---------------- scratch (device globals; no allocation allowed) -------------
__device__ float g_Qh[MM * DD];
__device__ float g_Kh[MM * DD];
__device__ float g_Vh[MM * DD];
__device__ float g_Ctx[MM * DD];

// ---------------- GEMM: Y[m,n] = sum_k X[m,k] * W[n,k]  (x @ W^T) -------------
// TF32 wmma m16n16k8, fp32 accumulate. Block tile 128x128x16, 8 warps (64x32 each).
#define GBM 128
#define GBN 128
#define GBK 16
#define GLD (GBK + 4)   // 20 floats, 80B rows -> 16B-aligned fragment bases

__global__ __launch_bounds__(256, 2) void gemm_xwt_kernel(
    const float* __restrict__ X, const float* __restrict__ W, float* __restrict__ Y)
{
    __shared__ __align__(16) float As[GBM][GLD];
    __shared__ __align__(16) float Bs[GBN][GLD];

    const int tid  = threadIdx.x;
    const int warp = tid >> 5;
    const int wm   = warp >> 2;   // 0..1  (64-row band)
    const int wn   = warp & 3;    // 0..3  (32-col band)
    const int m0   = blockIdx.y * GBM;
    const int n0   = blockIdx.x * GBN;

    wmma::fragment<wmma::accumulator, 16, 16, 8, float> c[4][2];
#pragma unroll
    for (int i = 0; i < 4; i++)
#pragma unroll
        for (int j = 0; j < 2; j++) wmma::fill_fragment(c[i][j], 0.f);

    const float* Xg = X + (size_t)m0 * DD;
    const float* Wg = W + (size_t)n0 * DD;

    for (int k0 = 0; k0 < DD; k0 += GBK) {
        // 128 rows x 16 cols each for A and B = 512 float4 each, 256 threads
#pragma unroll
        for (int i = tid; i < GBM * (GBK / 4); i += 256) {
            int r = i >> 2, c4 = i & 3;
            *(float4*)&As[r][c4 * 4] = *(const float4*)(Xg + (size_t)r * DD + k0 + c4 * 4);
            *(float4*)&Bs[r][c4 * 4] = *(const float4*)(Wg + (size_t)r * DD + k0 + c4 * 4);
        }
        __syncthreads();

#pragma unroll
        for (int kk = 0; kk < GBK; kk += 8) {
            wmma::fragment<wmma::matrix_a, 16, 16, 8, wmma::precision::tf32, wmma::row_major> a[4];
            wmma::fragment<wmma::matrix_b, 16, 16, 8, wmma::precision::tf32, wmma::col_major> b[2];
#pragma unroll
            for (int i = 0; i < 4; i++) {
                wmma::load_matrix_sync(a[i], &As[wm * 64 + i * 16][kk], GLD);
#pragma unroll
                for (int t = 0; t < a[i].num_elements; t++)
                    a[i].x[t] = wmma::__float_to_tf32(a[i].x[t]);
            }
#pragma unroll
            for (int j = 0; j < 2; j++) {
                // col_major view: element (k,n) at Bs[n0+n][kk+k]  => B[k][n] = W[n][k]
                wmma::load_matrix_sync(b[j], &Bs[wn * 32 + j * 16][kk], GLD);
#pragma unroll
                for (int t = 0; t < b[j].num_elements; t++)
                    b[j].x[t] = wmma::__float_to_tf32(b[j].x[t]);
            }
#pragma unroll
            for (int i = 0; i < 4; i++)
#pragma unroll
                for (int j = 0; j < 2; j++)
                    wmma::mma_sync(c[i][j], a[i], b[j], c[i][j]);
        }
        __syncthreads();
    }

    float* Yg = Y + (size_t)(m0 + wm * 64) * DD + n0 + wn * 32;
#pragma unroll
    for (int i = 0; i < 4; i++)
#pragma unroll
        for (int j = 0; j < 2; j++)
            wmma::store_matrix_sync(Yg + (size_t)i * 16 * DD + j * 16, c[i][j], DD,
                                    wmma::mem_row_major);
}

// ---------------- bias add (vectorized, in place) ----------------------------
__global__ void bias_add_kernel(float* __restrict__ Y, const float* __restrict__ b)
{
    int i = blockIdx.x * blockDim.x + threadIdx.x;   // float4 index
    float4 y = ((float4*)Y)[i];
    int col = (i * 4) & (DD - 1);
    const float4 bb = *(const float4*)(b + col);
    y.x += bb.x; y.y += bb.y; y.z += bb.z; y.w += bb.w;
    ((float4*)Y)[i] = y;
}

// ---------------- flash attention (per (b,h), 64 q-rows per block) -----------
// 4 warps; each warp owns a 16-row band for QK^T, softmax and PV.
// O accumulator lives in smem (fp32) so per-row online-softmax rescaling never
// touches the opaque wmma accumulator layout.
#define ALD 72   // 64 + 8 pad (288B rows: 16B aligned, bank-skewed)
#define ATT_SMEM_BYTES ((5 * 64 * ALD + 128) * (int)sizeof(float))

__global__ __launch_bounds__(128) void attn_kernel(
    const float* __restrict__ Qh, const float* __restrict__ Kh,
    const float* __restrict__ Vh, float* __restrict__ Ctx)
{
    extern __shared__ __align__(16) float sm[];
    float* Qs  = sm;
    float* Ks  = Qs + 64 * ALD;
    float* Vs  = Ks + 64 * ALD;
    float* Ss  = Vs + 64 * ALD;
    float* Os  = Ss + 64 * ALD;
    float* m_s = Os + 64 * ALD;   // 64
    float* l_s = m_s + 64;        // 64

    const int tid  = threadIdx.x;
    const int warp = tid >> 5;
    const int lane = tid & 31;
    const int qt   = blockIdx.x;        // 0..31 q tile
    const int bh   = blockIdx.y;        // 0..31 (b*H + h)
    const int b    = bh >> 4;
    const int h    = bh & 15;

    const size_t rowQ0 = (size_t)(b * SS + qt * 64);
    const size_t colH  = (size_t)h * DKK;
    const float* Qg  = Qh + rowQ0 * DD + colH;
    const float* Kg0 = Kh + (size_t)(b * SS) * DD + colH;
    const float* Vg0 = Vh + (size_t)(b * SS) * DD + colH;

    // load Q tile + zero O
#pragma unroll
    for (int i = tid; i < 64 * 16; i += 128) {
        int r = i >> 4, c4 = i & 15;
        *(float4*)&Qs[r * ALD + c4 * 4] = *(const float4*)(Qg + (size_t)r * DD + c4 * 4);
        float4 z = make_float4(0.f, 0.f, 0.f, 0.f);
        *(float4*)&Os[r * ALD + c4 * 4] = z;
    }
    if (tid < 64) { m_s[tid] = -INFINITY; l_s[tid] = 0.f; }
    __syncthreads();

    const float scale = 0.125f;  // 1/sqrt(64)

    for (int kt = 0; kt < SS / 64; kt++) {
        const float* Kg = Kg0 + (size_t)(kt * 64) * DD;
        const float* Vg = Vg0 + (size_t)(kt * 64) * DD;
#pragma unroll
        for (int i = tid; i < 64 * 16; i += 128) {
            int r = i >> 4, c4 = i & 15;
            *(float4*)&Ks[r * ALD + c4 * 4] = *(const float4*)(Kg + (size_t)r * DD + c4 * 4);
            *(float4*)&Vs[r * ALD + c4 * 4] = *(const float4*)(Vg + (size_t)r * DD + c4 * 4);
        }
        __syncthreads();

        // ---- S = Q K^T for this warp's 16 rows ----
        {
            wmma::fragment<wmma::accumulator, 16, 16, 8, float> c[4];
#pragma unroll
            for (int j = 0; j < 4; j++) wmma::fill_fragment(c[j], 0.f);
#pragma unroll
            for (int kk = 0; kk < DKK; kk += 8) {
                wmma::fragment<wmma::matrix_a, 16, 16, 8, wmma::precision::tf32, wmma::row_major> a;
                wmma::load_matrix_sync(a, &Qs[(warp * 16) * ALD + kk], ALD);
#pragma unroll
                for (int t = 0; t < a.num_elements; t++) a.x[t] = wmma::__float_to_tf32(a.x[t]);
#pragma unroll
                for (int j = 0; j < 4; j++) {
                    wmma::fragment<wmma::matrix_b, 16, 16, 8, wmma::precision::tf32, wmma::col_major> bf;
                    wmma::load_matrix_sync(bf, &Ks[(j * 16) * ALD + kk], ALD);
#pragma unroll
                    for (int t = 0; t < bf.num_elements; t++) bf.x[t] = wmma::__float_to_tf32(bf.x[t]);
                    wmma::mma_sync(c[j], a, bf, c[j]);
                }
            }
#pragma unroll
            for (int j = 0; j < 4; j++)
                wmma::store_matrix_sync(&Ss[(warp * 16) * ALD + j * 16], c[j], ALD,
                                        wmma::mem_row_major);
        }
        __syncwarp();

        // ---- online softmax on this warp's 16 rows (lane covers 2 cols) ----
        for (int r = 0; r < 16; r++) {
            const int row = warp * 16 + r;
            float s0 = Ss[row * ALD + lane]      * scale;
            float s1 = Ss[row * ALD + lane + 32] * scale;
            float mx = fmaxf(s0, s1);
#pragma unroll
            for (int o = 16; o > 0; o >>= 1) mx = fmaxf(mx, __shfl_xor_sync(0xffffffffu, mx, o));
            const float m_old = m_s[row];
            const float m_new = fmaxf(m_old, mx);
            const float p0 = __expf(s0 - m_new);
            const float p1 = __expf(s1 - m_new);
            float rs = p0 + p1;
#pragma unroll
            for (int o = 16; o > 0; o >>= 1) rs += __shfl_xor_sync(0xffffffffu, rs, o);
            const float alpha = __expf(m_old - m_new);
            if (lane == 0) { l_s[row] = l_s[row] * alpha + rs; m_s[row] = m_new; }
            Ss[row * ALD + lane]       = p0;
            Ss[row * ALD + lane + 32]  = p1;
            Os[row * ALD + lane]      *= alpha;
            Os[row * ALD + lane + 32] *= alpha;
        }
        __syncwarp();

        // ---- O += P V for this warp's 16 rows ----
        {
            wmma::fragment<wmma::accumulator, 16, 16, 8, float> c[4];
#pragma unroll
            for (int j = 0; j < 4; j++)
                wmma::load_matrix_sync(c[j], &Os[(warp * 16) * ALD + j * 16], ALD,
                                       wmma::mem_row_major);
#pragma unroll
            for (int kk = 0; kk < 64; kk += 8) {
                wmma::fragment<wmma::matrix_a, 16, 16, 8, wmma::precision::tf32, wmma::row_major> a;
                wmma::load_matrix_sync(a, &Ss[(warp * 16) * ALD + kk], ALD);
#pragma unroll
                for (int t = 0; t < a.num_elements; t++) a.x[t] = wmma::__float_to_tf32(a.x[t]);
#pragma unroll
                for (int j = 0; j < 4; j++) {
                    wmma::fragment<wmma::matrix_b, 16, 16, 8, wmma::precision::tf32, wmma::row_major> bf;
                    wmma::load_matrix_sync(bf, &Vs[kk * ALD + j * 16], ALD);
#pragma unroll
                    for (int t = 0; t < bf.num_elements; t++) bf.x[t] = wmma::__float_to_tf32(bf.x[t]);
                    wmma::mma_sync(c[j], a, bf, c[j]);
                }
            }
#pragma unroll
            for (int j = 0; j < 4; j++)
                wmma::store_matrix_sync(&Os[(warp * 16) * ALD + j * 16], c[j], ALD,
                                        wmma::mem_row_major);
        }
        __syncthreads();   // before Ks/Vs get overwritten next iter
    }

    // epilogue: ctx = O / l
    float* Cg = Ctx + rowQ0 * DD + colH;
#pragma unroll
    for (int i = tid; i < 64 * 64; i += 128) {
        int r = i >> 6, c = i & 63;
        Cg[(size_t)r * DD + c] = Os[r * ALD + c] * (1.f / l_s[r]);
    }
}

// ---------------- launch ------------------------------------------------------
extern "C" void kernel_launch(void* const* d_in, const int* /*in_sizes*/, int /*n_in*/,
                              void* d_out, int /*out_size*/)
{
    const float* q  = (const float*)d_in[0];
    const float* k  = (const float*)d_in[1];
    const float* v  = (const float*)d_in[2];
    const float* Wq = (const float*)d_in[3];
    const float* bq = (const float*)d_in[4];
    const float* Wk = (const float*)d_in[5];
    const float* bk = (const float*)d_in[6];
    const float* Wv = (const float*)d_in[7];
    const float* bv = (const float*)d_in[8];
    const float* Wo = (const float*)d_in[9];
    const float* bo = (const float*)d_in[10];
    float* out = (float*)d_out;

    float *Qh, *Kh, *Vh, *Ctx;
    cudaGetSymbolAddress((void**)&Qh,  g_Qh);
    cudaGetSymbolAddress((void**)&Kh,  g_Kh);
    cudaGetSymbolAddress((void**)&Vh,  g_Vh);
    cudaGetSymbolAddress((void**)&Ctx, g_Ctx);

    cudaFuncSetAttribute(attn_kernel, cudaFuncAttributeMaxDynamicSharedMemorySize,
                         ATT_SMEM_BYTES);

    const dim3 gg(DD / GBN, MM / GBM);       // (8, 32)
    const int  biasBlocks = (MM * DD / 4) / 256;

    // projections
    gemm_xwt_kernel<<<gg, 256>>>(q, Wq, Qh);
    gemm_xwt_kernel<<<gg, 256>>>(k, Wk, Kh);
    gemm_xwt_kernel<<<gg, 256>>>(v, Wv, Vh);
    bias_add_kernel<<<biasBlocks, 256>>>(Qh, bq);
    bias_add_kernel<<<biasBlocks, 256>>>(Kh, bk);
    bias_add_kernel<<<biasBlocks, 256>>>(Vh, bv);

    // attention
    attn_kernel<<<dim3(SS / 64, BB * HH), 128, ATT_SMEM_BYTES>>>(Qh, Kh, Vh, Ctx);

    // output projection
    gemm_xwt_kernel<<<gg, 256>>>(Ctx, Wo, out);
    bias_add_kernel<<<biasBlocks, 256>>>(out, bo);
}

// round 2
// speedup vs baseline: 3.3002x; 3.3002x over previous
#include <cuda_runtime.h>
#include <math.h>
#include <stdint.h>

// Problem shape (fixed by the reference)
#define BB   2
#define SS   2048
#define DD   1024
#define HH   16
#define DKK  64
#define MM   (BB * SS)   // 4096 rows

// ---------------- scratch (device globals; no allocation allowed) -------------
__device__ float g_Qh[MM * DD];
__device__ float g_Kh[MM * DD];
__device__ float g_Vh[MM * DD];
__device__ float g_Ctx[MM * DD];

// ---------------- PTX helpers -------------------------------------------------
__device__ __forceinline__ uint32_t f2tf32(float x) {
    uint32_t r;
    asm("cvt.rna.tf32.f32 %0, %1;\n" : "=r"(r) : "f"(x));
    return r;
}

// D(16x8) += A(16x8,tf32,row) * B(8x8,tf32,col)
__device__ __forceinline__ void mma_tf32(float c[4], const uint32_t a[4], const uint32_t b[2]) {
    asm volatile(
        "mma.sync.aligned.m16n8k8.row.col.f32.tf32.tf32.f32 "
        "{%0,%1,%2,%3}, {%4,%5,%6,%7}, {%8,%9}, {%0,%1,%2,%3};\n"
        : "+f"(c[0]), "+f"(c[1]), "+f"(c[2]), "+f"(c[3])
        : "r"(a[0]), "r"(a[1]), "r"(a[2]), "r"(a[3]), "r"(b[0]), "r"(b[1]));
}

__device__ __forceinline__ void cp_async16(void* smem, const void* gmem) {
    uint32_t s = (uint32_t)__cvta_generic_to_shared(smem);
    asm volatile("cp.async.cg.shared.global [%0], [%1], 16;\n" :: "r"(s), "l"(gmem));
}
__device__ __forceinline__ void cp_commit()  { asm volatile("cp.async.commit_group;\n"); }
__device__ __forceinline__ void cp_wait0()   { asm volatile("cp.async.wait_group 0;\n"); }

// ---------------- GEMM: Y[m,n] = sum_k X[m,k]*W[n,k] + bias[n] ----------------
// Raw mma m16n8k8 TF32. Block 128x128, GBK=32, 2-stage cp.async pipeline.
// 8 warps in 2(m) x 4(n); warp tile 64x32 -> c[4 mtiles][4 ntiles][4].
#define GBM 128
#define GBN 128
#define GBK 32
#define GLD 36   // 32+4 pad: row stride = 36 words == 4 mod 32 -> conflict-free frag loads
#define GEMM_SMEM_BYTES (2 * (GBM + GBN) * GLD * 4)

__global__ __launch_bounds__(256, 2) void gemm_bias_kernel(
    const float* __restrict__ X, const float* __restrict__ W,
    const float* __restrict__ bias, float* __restrict__ Y)
{
    extern __shared__ __align__(16) float sm[];
    float* As = sm;                       // [2][128][GLD]
    float* Bs = sm + 2 * GBM * GLD;       // [2][128][GLD]

    const int tid  = threadIdx.x;
    const int warp = tid >> 5, lane = tid & 31;
    const int g = lane >> 2, tg = lane & 3;
    const int wm = warp >> 2, wn = warp & 3;
    const int m0 = blockIdx.y * GBM, n0 = blockIdx.x * GBN;

    float c[4][4][4];
#pragma unroll
    for (int i = 0; i < 4; i++)
#pragma unroll
        for (int j = 0; j < 4; j++)
#pragma unroll
            for (int t = 0; t < 4; t++) c[i][j][t] = 0.f;

    const float* Xg = X + (size_t)m0 * DD;
    const float* Wg = W + (size_t)n0 * DD;

    // stage loader: 128 rows x 32 cols = 1024 float4 per matrix
#define GEMM_LOAD_STAGE(s, k0)                                                        \
    do {                                                                              \
        _Pragma("unroll")                                                             \
        for (int i = tid; i < GBM * (GBK / 4); i += 256) {                            \
            int r = i >> 3, c4 = i & 7;                                               \
            cp_async16(&As[(s) * GBM * GLD + r * GLD + c4 * 4],                       \
                       Xg + (size_t)r * DD + (k0) + c4 * 4);                          \
            cp_async16(&Bs[(s) * GBN * GLD + r * GLD + c4 * 4],                       \
                       Wg + (size_t)r * DD + (k0) + c4 * 4);                          \
        }                                                                             \
    } while (0)

    GEMM_LOAD_STAGE(0, 0);
    cp_commit(); cp_wait0();
    __syncthreads();

    const int nK = DD / GBK;   // 32
    for (int kt = 0; kt < nK; kt++) {
        const int s = kt & 1;
        if (kt + 1 < nK) { GEMM_LOAD_STAGE(s ^ 1, (kt + 1) * GBK); cp_commit(); }

        const float* A = As + s * GBM * GLD;
        const float* B = Bs + s * GBN * GLD;
#pragma unroll
        for (int kk = 0; kk < GBK; kk += 8) {
            uint32_t a[4][4], b[4][2];
#pragma unroll
            for (int mi = 0; mi < 4; mi++) {
                int r = (wm * 64 + mi * 16 + g) * GLD;
                a[mi][0] = f2tf32(A[r + kk + tg]);
                a[mi][1] = f2tf32(A[r + 8 * GLD + kk + tg]);
                a[mi][2] = f2tf32(A[r + kk + tg + 4]);
                a[mi][3] = f2tf32(A[r + 8 * GLD + kk + tg + 4]);
            }
#pragma unroll
            for (int nj = 0; nj < 4; nj++) {
                int rn = (wn * 32 + nj * 8 + g) * GLD;
                b[nj][0] = f2tf32(B[rn + kk + tg]);
                b[nj][1] = f2tf32(B[rn + kk + tg + 4]);
            }
#pragma unroll
            for (int mi = 0; mi < 4; mi++)
#pragma unroll
                for (int nj = 0; nj < 4; nj++)
                    mma_tf32(c[mi][nj], a[mi], b[nj]);
        }
        cp_wait0();
        __syncthreads();
    }

    // epilogue: + bias, store (accumulator layout: c0:(g,2tg) c1:(g,2tg+1) c2:(g+8,2tg) c3:(g+8,2tg+1))
#pragma unroll
    for (int nj = 0; nj < 4; nj++) {
        const int coln = n0 + wn * 32 + nj * 8 + 2 * tg;
        const float2 bb = *(const float2*)(bias + coln);
#pragma unroll
        for (int mi = 0; mi < 4; mi++) {
            const int row = m0 + wm * 64 + mi * 16 + g;
            float2 v0 = make_float2(c[mi][nj][0] + bb.x, c[mi][nj][1] + bb.y);
            float2 v1 = make_float2(c[mi][nj][2] + bb.x, c[mi][nj][3] + bb.y);
            *(float2*)(Y + (size_t)row * DD + coln)       = v0;
            *(float2*)(Y + (size_t)(row + 8) * DD + coln) = v1;
        }
    }
#undef GEMM_LOAD_STAGE
}

// ---------------- flash attention: register softmax, raw mma ------------------
// Block: 128 threads (4 warps). BM=64 q rows (16/warp), KV tile 64.
// S and O live in mma accumulator registers; stats (m,l) in registers per thread.
// P goes through a per-warp smem slab to re-enter mma as an A-fragment.
#define KLD 68   // k-major tiles: stride == 4 mod 32 -> conflict-free frag loads
#define VLD 72   // V (n-major access): stride == 8 mod 32 -> conflict-free
#define ATT_SMEM_FLOATS (2 * 64 * KLD + 2 * 64 * VLD + 64 * KLD)
#define ATT_SMEM_BYTES  (ATT_SMEM_FLOATS * 4)

__global__ __launch_bounds__(128, 2) void attn_kernel(
    const float* __restrict__ Qh, const float* __restrict__ Kh,
    const float* __restrict__ Vh, float* __restrict__ Ctx)
{
    extern __shared__ __align__(16) float sm[];
    float* Ks = sm;                          // [2][64][KLD]
    float* Vs = Ks + 2 * 64 * KLD;           // [2][64][VLD]
    float* Ss = Vs + 2 * 64 * VLD;           // [64][KLD]  (Q staging, then P per warp)

    const int tid  = threadIdx.x;
    const int warp = tid >> 5, lane = tid & 31;
    const int g = lane >> 2, tg = lane & 3;
    const int qt = blockIdx.x;          // 0..31
    const int bh = blockIdx.y;          // 0..31
    const int b  = bh >> 4;
    const int h  = bh & 15;

    const size_t rowQ0 = (size_t)(b * SS + qt * 64);
    const size_t colH  = (size_t)h * DKK;
    const float* Qg  = Qh + rowQ0 * DD + colH;
    const float* Kg0 = Kh + (size_t)(b * SS) * DD + colH;
    const float* Vg0 = Vh + (size_t)(b * SS) * DD + colH;

    // prefetch K/V tile 0 (overlaps with Q staging)
#define ATT_LOAD_STAGE(s, kt)                                                          \
    do {                                                                               \
        const float* Kg = Kg0 + (size_t)((kt) * 64) * DD;                              \
        const float* Vg = Vg0 + (size_t)((kt) * 64) * DD;                              \
        _Pragma("unroll")                                                              \
        for (int i = tid; i < 64 * 16; i += 128) {                                     \
            int r = i >> 4, c4 = i & 15;                                               \
            cp_async16(&Ks[(s) * 64 * KLD + r * KLD + c4 * 4],                         \
                       Kg + (size_t)r * DD + c4 * 4);                                  \
            cp_async16(&Vs[(s) * 64 * VLD + r * VLD + c4 * 4],                         \
                       Vg + (size_t)r * DD + c4 * 4);                                  \
        }                                                                              \
    } while (0)

    ATT_LOAD_STAGE(0, 0);
    cp_commit();

    // stage Q into Ss, then into tf32 A-fragment registers (held for all k-tiles)
#pragma unroll
    for (int i = tid; i < 64 * 16; i += 128) {
        int r = i >> 4, c4 = i & 15;
        *(float4*)&Ss[r * KLD + c4 * 4] = *(const float4*)(Qg + (size_t)r * DD + c4 * 4);
    }
    __syncthreads();

    uint32_t aq[8][4];
    {
        const int rA = (warp * 16 + g) * KLD;
#pragma unroll
        for (int kk = 0; kk < 8; kk++) {
            aq[kk][0] = f2tf32(Ss[rA + 8 * kk + tg]);
            aq[kk][1] = f2tf32(Ss[rA + 8 * KLD + 8 * kk + tg]);
            aq[kk][2] = f2tf32(Ss[rA + 8 * kk + tg + 4]);
            aq[kk][3] = f2tf32(Ss[rA + 8 * KLD + 8 * kk + tg + 4]);
        }
    }
    __syncthreads();   // Ss free for P use

    float o[8][4];
#pragma unroll
    for (int j = 0; j < 8; j++)
#pragma unroll
        for (int t = 0; t < 4; t++) o[j][t] = 0.f;
    float mA = -INFINITY, mB = -INFINITY, lA = 0.f, lB = 0.f;

    const float scale = 0.125f;  // 1/sqrt(64)
    float* Sw = Ss + (warp * 16) * KLD;   // this warp's 16-row P slab

    cp_wait0();
    __syncthreads();

    for (int kt = 0; kt < SS / 64; kt++) {
        const int s = kt & 1;
        if (kt + 1 < SS / 64) { ATT_LOAD_STAGE(s ^ 1, kt + 1); cp_commit(); }

        const float* K = Ks + s * 64 * KLD;
        const float* V = Vs + s * 64 * VLD;

        // ---- S = Q K^T (16 x 64 per warp) ----
        float sc[8][4];
#pragma unroll
        for (int j = 0; j < 8; j++)
#pragma unroll
            for (int t = 0; t < 4; t++) sc[j][t] = 0.f;

#pragma unroll
        for (int kk = 0; kk < 8; kk++) {
#pragma unroll
            for (int j = 0; j < 8; j++) {
                uint32_t bfr[2];
                const int rn = (8 * j + g) * KLD + 8 * kk + tg;
                bfr[0] = f2tf32(K[rn]);
                bfr[1] = f2tf32(K[rn + 4]);
                mma_tf32(sc[j], aq[kk], bfr);
            }
        }

        // ---- online softmax in registers ----
        // rows: rowA = warp*16+g (sc[j][0..1]); rowB = rowA+8 (sc[j][2..3])
        float mxA = -INFINITY, mxB = -INFINITY;
#pragma unroll
        for (int j = 0; j < 8; j++) {
            sc[j][0] *= scale; sc[j][1] *= scale; sc[j][2] *= scale; sc[j][3] *= scale;
            mxA = fmaxf(mxA, fmaxf(sc[j][0], sc[j][1]));
            mxB = fmaxf(mxB, fmaxf(sc[j][2], sc[j][3]));
        }
        mxA = fmaxf(mxA, __shfl_xor_sync(0xffffffffu, mxA, 1));
        mxA = fmaxf(mxA, __shfl_xor_sync(0xffffffffu, mxA, 2));
        mxB = fmaxf(mxB, __shfl_xor_sync(0xffffffffu, mxB, 1));
        mxB = fmaxf(mxB, __shfl_xor_sync(0xffffffffu, mxB, 2));

        const float mA_new = fmaxf(mA, mxA);
        const float mB_new = fmaxf(mB, mxB);
        const float alphaA = __expf(mA - mA_new);
        const float alphaB = __expf(mB - mB_new);

        float sumA = 0.f, sumB = 0.f;
#pragma unroll
        for (int j = 0; j < 8; j++) {
            sc[j][0] = __expf(sc[j][0] - mA_new);
            sc[j][1] = __expf(sc[j][1] - mA_new);
            sc[j][2] = __expf(sc[j][2] - mB_new);
            sc[j][3] = __expf(sc[j][3] - mB_new);
            sumA += sc[j][0] + sc[j][1];
            sumB += sc[j][2] + sc[j][3];
        }
        sumA += __shfl_xor_sync(0xffffffffu, sumA, 1);
        sumA += __shfl_xor_sync(0xffffffffu, sumA, 2);
        sumB += __shfl_xor_sync(0xffffffffu, sumB, 1);
        sumB += __shfl_xor_sync(0xffffffffu, sumB, 2);

        lA = lA * alphaA + sumA;  mA = mA_new;
        lB = lB * alphaB + sumB;  mB = mB_new;

        // rescale O
#pragma unroll
        for (int j = 0; j < 8; j++) {
            o[j][0] *= alphaA; o[j][1] *= alphaA;
            o[j][2] *= alphaB; o[j][3] *= alphaB;
        }

        // ---- P -> smem (per-warp slab), then O += P V ----
#pragma unroll
        for (int j = 0; j < 8; j++) {
            *(float2*)&Sw[g * KLD + 8 * j + 2 * tg]           = make_float2(sc[j][0], sc[j][1]);
            *(float2*)&Sw[(g + 8) * KLD + 8 * j + 2 * tg]     = make_float2(sc[j][2], sc[j][3]);
        }
        __syncwarp();

#pragma unroll
        for (int kk = 0; kk < 8; kk++) {
            uint32_t pa[4];
            pa[0] = f2tf32(Sw[g * KLD + 8 * kk + tg]);
            pa[1] = f2tf32(Sw[(g + 8) * KLD + 8 * kk + tg]);
            pa[2] = f2tf32(Sw[g * KLD + 8 * kk + tg + 4]);
            pa[3] = f2tf32(Sw[(g + 8) * KLD + 8 * kk + tg + 4]);
#pragma unroll
            for (int j = 0; j < 8; j++) {
                uint32_t bfr[2];
                const int rv = (8 * kk + tg) * VLD + 8 * j + g;
                bfr[0] = f2tf32(V[rv]);
                bfr[1] = f2tf32(V[rv + 4 * VLD]);
                mma_tf32(o[j], pa, bfr);
            }
        }

        cp_wait0();
        __syncthreads();   // guard K/V/Ss buffer reuse
    }

    // ---- epilogue: ctx = O / l ----
    const float invA = 1.f / lA, invB = 1.f / lB;
    float* Cg = Ctx + rowQ0 * DD + colH;
    const int rowA = warp * 16 + g;
#pragma unroll
    for (int j = 0; j < 8; j++) {
        const int col = 8 * j + 2 * tg;
        *(float2*)(Cg + (size_t)rowA * DD + col) =
            make_float2(o[j][0] * invA, o[j][1] * invA);
        *(float2*)(Cg + (size_t)(rowA + 8) * DD + col) =
            make_float2(o[j][2] * invB, o[j][3] * invB);
    }
#undef ATT_LOAD_STAGE
}

// ---------------- launch ------------------------------------------------------
extern "C" void kernel_launch(void* const* d_in, const int* /*in_sizes*/, int /*n_in*/,
                              void* d_out, int /*out_size*/)
{
    const float* q  = (const float*)d_in[0];
    const float* k  = (const float*)d_in[1];
    const float* v  = (const float*)d_in[2];
    const float* Wq = (const float*)d_in[3];
    const float* bq = (const float*)d_in[4];
    const float* Wk = (const float*)d_in[5];
    const float* bk = (const float*)d_in[6];
    const float* Wv = (const float*)d_in[7];
    const float* bv = (const float*)d_in[8];
    const float* Wo = (const float*)d_in[9];
    const float* bo = (const float*)d_in[10];
    float* out = (float*)d_out;

    float *Qh, *Kh, *Vh, *Ctx;
    cudaGetSymbolAddress((void**)&Qh,  g_Qh);
    cudaGetSymbolAddress((void**)&Kh,  g_Kh);
    cudaGetSymbolAddress((void**)&Vh,  g_Vh);
    cudaGetSymbolAddress((void**)&Ctx, g_Ctx);

    cudaFuncSetAttribute(gemm_bias_kernel, cudaFuncAttributeMaxDynamicSharedMemorySize,
                         GEMM_SMEM_BYTES);
    cudaFuncSetAttribute(attn_kernel, cudaFuncAttributeMaxDynamicSharedMemorySize,
                         ATT_SMEM_BYTES);

    const dim3 gg(DD / GBN, MM / GBM);   // (8, 32)

    gemm_bias_kernel<<<gg, 256, GEMM_SMEM_BYTES>>>(q, Wq, bq, Qh);
    gemm_bias_kernel<<<gg, 256, GEMM_SMEM_BYTES>>>(k, Wk, bk, Kh);
    gemm_bias_kernel<<<gg, 256, GEMM_SMEM_BYTES>>>(v, Wv, bv, Vh);

    attn_kernel<<<dim3(SS / 64, BB * HH), 128, ATT_SMEM_BYTES>>>(Qh, Kh, Vh, Ctx);

    gemm_bias_kernel<<<gg, 256, GEMM_SMEM_BYTES>>>(Ctx, Wo, bo, out);
}

// round 4
// speedup vs baseline: 3.6799x; 1.1151x over previous
#include <cuda_runtime.h>
#include <math.h>
#include <stdint.h>

// Problem shape (fixed by the reference)
#define BB   2
#define SS   2048
#define DD   1024
#define HH   16
#define DKK  64
#define MM   (BB * SS)   // 4096 rows

// ---------------- scratch (device globals; no allocation allowed) -------------
__device__ float g_Qh[MM * DD];
__device__ float g_Kh[MM * DD];
__device__ float g_Vh[MM * DD];
__device__ float g_Ctx[MM * DD];

// ---------------- PTX helpers -------------------------------------------------
__device__ __forceinline__ uint32_t f2tf32(float x) {
    uint32_t r;
    asm("cvt.rna.tf32.f32 %0, %1;\n" : "=r"(r) : "f"(x));
    return r;
}

// D(16x8) += A(16x8,tf32,row) * B(8x8,tf32,col)
__device__ __forceinline__ void mma_tf32(float c[4], const uint32_t a[4], const uint32_t b[2]) {
    asm volatile(
        "mma.sync.aligned.m16n8k8.row.col.f32.tf32.tf32.f32 "
        "{%0,%1,%2,%3}, {%4,%5,%6,%7}, {%8,%9}, {%0,%1,%2,%3};\n"
        : "+f"(c[0]), "+f"(c[1]), "+f"(c[2]), "+f"(c[3])
        : "r"(a[0]), "r"(a[1]), "r"(a[2]), "r"(a[3]), "r"(b[0]), "r"(b[1]));
}

__device__ __forceinline__ void cp_async16(void* smem, const void* gmem) {
    uint32_t s = (uint32_t)__cvta_generic_to_shared(smem);
    asm volatile("cp.async.cg.shared.global [%0], [%1], 16;\n" :: "r"(s), "l"(gmem));
}
__device__ __forceinline__ void cp_commit()  { asm volatile("cp.async.commit_group;\n"); }
__device__ __forceinline__ void cp_wait0()   { asm volatile("cp.async.wait_group 0;\n"); }

// ---------------- GEMM: Y[m,n] = sum_k X[m,k]*W[n,k] + bias[n] ----------------
// Raw mma m16n8k8 TF32. Block 128x128, GBK=32, 2-stage cp.async pipeline.
// 8 warps in 2(m) x 4(n); warp tile 64x32 -> c[4 mtiles][4 ntiles][4].
// CVTA: convert A-side fp32->tf32 at fragment load (false when X is pre-rounded).
// RND : round the output to tf32 bits before storing (for attention consumers).
#define GBM 128
#define GBN 128
#define GBK 32
#define GLD 36   // 32+4 pad: row stride = 36 words == 4 mod 32 -> conflict-free frag loads
#define GEMM_SMEM_BYTES (2 * (GBM + GBN) * GLD * 4)

template<bool CVTA, bool RND>
__global__ __launch_bounds__(256, 2) void gemm_bias_kernel(
    const float* __restrict__ X, const float* __restrict__ W,
    const float* __restrict__ bias, float* __restrict__ Y)
{
    extern __shared__ __align__(16) float sm[];
    float* As = sm;                       // [2][128][GLD]
    float* Bs = sm + 2 * GBM * GLD;       // [2][128][GLD]

    const int tid  = threadIdx.x;
    const int warp = tid >> 5, lane = tid & 31;
    const int g = lane >> 2, tg = lane & 3;
    const int wm = warp >> 2, wn = warp & 3;
    const int m0 = blockIdx.y * GBM, n0 = blockIdx.x * GBN;

    float c[4][4][4];
#pragma unroll
    for (int i = 0; i < 4; i++)
#pragma unroll
        for (int j = 0; j < 4; j++)
#pragma unroll
            for (int t = 0; t < 4; t++) c[i][j][t] = 0.f;

    const float* Xg = X + (size_t)m0 * DD;
    const float* Wg = W + (size_t)n0 * DD;

#define GEMM_LOAD_STAGE(s, k0)                                                        \
    do {                                                                              \
        _Pragma("unroll")                                                             \
        for (int i = tid; i < GBM * (GBK / 4); i += 256) {                            \
            int r = i >> 3, c4 = i & 7;                                               \
            cp_async16(&As[(s) * GBM * GLD + r * GLD + c4 * 4],                       \
                       Xg + (size_t)r * DD + (k0) + c4 * 4);                          \
            cp_async16(&Bs[(s) * GBN * GLD + r * GLD + c4 * 4],                       \
                       Wg + (size_t)r * DD + (k0) + c4 * 4);                          \
        }                                                                             \
    } while (0)

    GEMM_LOAD_STAGE(0, 0);
    cp_commit(); cp_wait0();
    __syncthreads();

    const int nK = DD / GBK;   // 32
    for (int kt = 0; kt < nK; kt++) {
        const int s = kt & 1;
        if (kt + 1 < nK) { GEMM_LOAD_STAGE(s ^ 1, (kt + 1) * GBK); cp_commit(); }

        const float* A = As + s * GBM * GLD;
        const float* B = Bs + s * GBN * GLD;
#pragma unroll
        for (int kk = 0; kk < GBK; kk += 8) {
            uint32_t a[4][4], b[4][2];
#pragma unroll
            for (int mi = 0; mi < 4; mi++) {
                int r = (wm * 64 + mi * 16 + g) * GLD;
                if (CVTA) {
                    a[mi][0] = f2tf32(A[r + kk + tg]);
                    a[mi][1] = f2tf32(A[r + 8 * GLD + kk + tg]);
                    a[mi][2] = f2tf32(A[r + kk + tg + 4]);
                    a[mi][3] = f2tf32(A[r + 8 * GLD + kk + tg + 4]);
                } else {
                    a[mi][0] = __float_as_uint(A[r + kk + tg]);
                    a[mi][1] = __float_as_uint(A[r + 8 * GLD + kk + tg]);
                    a[mi][2] = __float_as_uint(A[r + kk + tg + 4]);
                    a[mi][3] = __float_as_uint(A[r + 8 * GLD + kk + tg + 4]);
                }
            }
#pragma unroll
            for (int nj = 0; nj < 4; nj++) {
                int rn = (wn * 32 + nj * 8 + g) * GLD;
                b[nj][0] = f2tf32(B[rn + kk + tg]);
                b[nj][1] = f2tf32(B[rn + kk + tg + 4]);
            }
#pragma unroll
            for (int mi = 0; mi < 4; mi++)
#pragma unroll
                for (int nj = 0; nj < 4; nj++)
                    mma_tf32(c[mi][nj], a[mi], b[nj]);
        }
        cp_wait0();
        __syncthreads();
    }

    // epilogue: + bias, (optional tf32 pre-round), store
#pragma unroll
    for (int nj = 0; nj < 4; nj++) {
        const int coln = n0 + wn * 32 + nj * 8 + 2 * tg;
        const float2 bb = *(const float2*)(bias + coln);
#pragma unroll
        for (int mi = 0; mi < 4; mi++) {
            const int row = m0 + wm * 64 + mi * 16 + g;
            float y00 = c[mi][nj][0] + bb.x, y01 = c[mi][nj][1] + bb.y;
            float y10 = c[mi][nj][2] + bb.x, y11 = c[mi][nj][3] + bb.y;
            if (RND) {
                y00 = __uint_as_float(f2tf32(y00));
                y01 = __uint_as_float(f2tf32(y01));
                y10 = __uint_as_float(f2tf32(y10));
                y11 = __uint_as_float(f2tf32(y11));
            }
            *(float2*)(Y + (size_t)row * DD + coln)       = make_float2(y00, y01);
            *(float2*)(Y + (size_t)(row + 8) * DD + coln) = make_float2(y10, y11);
        }
    }
#undef GEMM_LOAD_STAGE
}

// ---------------- flash attention: register softmax, raw mma ------------------
// Inputs Qh/Kh/Vh are PRE-ROUNDED to tf32 bits -> fragment loads are raw bit
// moves (no cvt). Scale 1/8 is folded into the Q fragments (exact: 2^-3).
// Block: 128 threads (4 warps). BM=64 q rows (16/warp), KV tile 64.
#define KLD 68   // k-major tiles: stride == 4 mod 32 -> conflict-free frag loads
#define VLD 72   // V (n-major access): stride == 8 mod 32 -> conflict-free
#define ATT_SMEM_FLOATS (2 * 64 * KLD + 2 * 64 * VLD + 64 * KLD)
#define ATT_SMEM_BYTES  (ATT_SMEM_FLOATS * 4)

__global__ __launch_bounds__(128, 2) void attn_kernel(
    const float* __restrict__ Qh, const float* __restrict__ Kh,
    const float* __restrict__ Vh, float* __restrict__ Ctx)
{
    extern __shared__ __align__(16) float sm[];
    float* Ks = sm;                          // [2][64][KLD]
    float* Vs = Ks + 2 * 64 * KLD;           // [2][64][VLD]
    float* Ss = Vs + 2 * 64 * VLD;           // [64][KLD]  (Q staging, then P per warp)

    const int tid  = threadIdx.x;
    const int warp = tid >> 5, lane = tid & 31;
    const int g = lane >> 2, tg = lane & 3;
    const int qt = blockIdx.x;          // 0..31
    const int bh = blockIdx.y;          // 0..31
    const int b  = bh >> 4;
    const int h  = bh & 15;

    const size_t rowQ0 = (size_t)(b * SS + qt * 64);
    const size_t colH  = (size_t)h * DKK;
    const float* Qg  = Qh + rowQ0 * DD + colH;
    const float* Kg0 = Kh + (size_t)(b * SS) * DD + colH;
    const float* Vg0 = Vh + (size_t)(b * SS) * DD + colH;

#define ATT_LOAD_STAGE(s, kt)                                                          \
    do {                                                                               \
        const float* Kg = Kg0 + (size_t)((kt) * 64) * DD;                              \
        const float* Vg = Vg0 + (size_t)((kt) * 64) * DD;                              \
        _Pragma("unroll")                                                              \
        for (int i = tid; i < 64 * 16; i += 128) {                                     \
            int r = i >> 4, c4 = i & 15;                                               \
            cp_async16(&Ks[(s) * 64 * KLD + r * KLD + c4 * 4],                         \
                       Kg + (size_t)r * DD + c4 * 4);                                  \
            cp_async16(&Vs[(s) * 64 * VLD + r * VLD + c4 * 4],                         \
                       Vg + (size_t)r * DD + c4 * 4);                                  \
        }                                                                              \
    } while (0)

    ATT_LOAD_STAGE(0, 0);
    cp_commit();

    // stage Q into Ss, then into A-fragment registers with the 1/8 scale folded in
#pragma unroll
    for (int i = tid; i < 64 * 16; i += 128) {
        int r = i >> 4, c4 = i & 15;
        *(float4*)&Ss[r * KLD + c4 * 4] = *(const float4*)(Qg + (size_t)r * DD + c4 * 4);
    }
    __syncthreads();

    uint32_t aq[8][4];
    {
        const int rA = (warp * 16 + g) * KLD;
        const float scale = 0.125f;   // exact power of two: tf32 stays tf32
#pragma unroll
        for (int kk = 0; kk < 8; kk++) {
            aq[kk][0] = __float_as_uint(Ss[rA + 8 * kk + tg] * scale);
            aq[kk][1] = __float_as_uint(Ss[rA + 8 * KLD + 8 * kk + tg] * scale);
            aq[kk][2] = __float_as_uint(Ss[rA + 8 * kk + tg + 4] * scale);
            aq[kk][3] = __float_as_uint(Ss[rA + 8 * KLD + 8 * kk + tg + 4] * scale);
        }
    }
    __syncthreads();   // Ss free for P use

    float o[8][4];
#pragma unroll
    for (int j = 0; j < 8; j++)
#pragma unroll
        for (int t = 0; t < 4; t++) o[j][t] = 0.f;
    float mA = -INFINITY, mB = -INFINITY, lA = 0.f, lB = 0.f;

    float* Sw = Ss + (warp * 16) * KLD;   // this warp's 16-row P slab

    cp_wait0();
    __syncthreads();

    for (int kt = 0; kt < SS / 64; kt++) {
        const int s = kt & 1;
        if (kt + 1 < SS / 64) { ATT_LOAD_STAGE(s ^ 1, kt + 1); cp_commit(); }

        const float* K = Ks + s * 64 * KLD;
        const float* V = Vs + s * 64 * VLD;

        // ---- S = (Q/8) K^T (16 x 64 per warp); K bits are already tf32 ----
        float sc[8][4];
#pragma unroll
        for (int j = 0; j < 8; j++)
#pragma unroll
            for (int t = 0; t < 4; t++) sc[j][t] = 0.f;

#pragma unroll
        for (int kk = 0; kk < 8; kk++) {
#pragma unroll
            for (int j = 0; j < 8; j++) {
                uint32_t bfr[2];
                const int rn = (8 * j + g) * KLD + 8 * kk + tg;
                bfr[0] = __float_as_uint(K[rn]);
                bfr[1] = __float_as_uint(K[rn + 4]);
                mma_tf32(sc[j], aq[kk], bfr);
            }
        }

        // ---- online softmax in registers ----
        float mxA = -INFINITY, mxB = -INFINITY;
#pragma unroll
        for (int j = 0; j < 8; j++) {
            mxA = fmaxf(mxA, fmaxf(sc[j][0], sc[j][1]));
            mxB = fmaxf(mxB, fmaxf(sc[j][2], sc[j][3]));
        }
        mxA = fmaxf(mxA, __shfl_xor_sync(0xffffffffu, mxA, 1));
        mxA = fmaxf(mxA, __shfl_xor_sync(0xffffffffu, mxA, 2));
        mxB = fmaxf(mxB, __shfl_xor_sync(0xffffffffu, mxB, 1));
        mxB = fmaxf(mxB, __shfl_xor_sync(0xffffffffu, mxB, 2));

        const float mA_new = fmaxf(mA, mxA);
        const float mB_new = fmaxf(mB, mxB);
        const float alphaA = __expf(mA - mA_new);
        const float alphaB = __expf(mB - mB_new);

        float sumA = 0.f, sumB = 0.f;
#pragma unroll
        for (int j = 0; j < 8; j++) {
            sc[j][0] = __expf(sc[j][0] - mA_new);
            sc[j][1] = __expf(sc[j][1] - mA_new);
            sc[j][2] = __expf(sc[j][2] - mB_new);
            sc[j][3] = __expf(sc[j][3] - mB_new);
            sumA += sc[j][0] + sc[j][1];
            sumB += sc[j][2] + sc[j][3];
        }
        sumA += __shfl_xor_sync(0xffffffffu, sumA, 1);
        sumA += __shfl_xor_sync(0xffffffffu, sumA, 2);
        sumB += __shfl_xor_sync(0xffffffffu, sumB, 1);
        sumB += __shfl_xor_sync(0xffffffffu, sumB, 2);

        lA = lA * alphaA + sumA;  mA = mA_new;
        lB = lB * alphaB + sumB;  mB = mB_new;

#pragma unroll
        for (int j = 0; j < 8; j++) {
            o[j][0] *= alphaA; o[j][1] *= alphaA;
            o[j][2] *= alphaB; o[j][3] *= alphaB;
        }

        // ---- P -> smem pre-rounded to tf32 bits, then O += P V ----
#pragma unroll
        for (int j = 0; j < 8; j++) {
            *(float2*)&Sw[g * KLD + 8 * j + 2 * tg] =
                make_float2(__uint_as_float(f2tf32(sc[j][0])),
                            __uint_as_float(f2tf32(sc[j][1])));
            *(float2*)&Sw[(g + 8) * KLD + 8 * j + 2 * tg] =
                make_float2(__uint_as_float(f2tf32(sc[j][2])),
                            __uint_as_float(f2tf32(sc[j][3])));
        }
        __syncwarp();

#pragma unroll
        for (int kk = 0; kk < 8; kk++) {
            uint32_t pa[4];
            pa[0] = __float_as_uint(Sw[g * KLD + 8 * kk + tg]);
            pa[1] = __float_as_uint(Sw[(g + 8) * KLD + 8 * kk + tg]);
            pa[2] = __float_as_uint(Sw[g * KLD + 8 * kk + tg + 4]);
            pa[3] = __float_as_uint(Sw[(g + 8) * KLD + 8 * kk + tg + 4]);
#pragma unroll
            for (int j = 0; j < 8; j++) {
                uint32_t bfr[2];
                const int rv = (8 * kk + tg) * VLD + 8 * j + g;
                bfr[0] = __float_as_uint(V[rv]);
                bfr[1] = __float_as_uint(V[rv + 4 * VLD]);
                mma_tf32(o[j], pa, bfr);
            }
        }

        cp_wait0();
        __syncthreads();   // guard K/V/Ss buffer reuse
    }

    // ---- epilogue: ctx = O / l, pre-rounded to tf32 for the final GEMM ----
    const float invA = 1.f / lA, invB = 1.f / lB;
    float* Cg = Ctx + rowQ0 * DD + colH;
    const int rowA = warp * 16 + g;
#pragma unroll
    for (int j = 0; j < 8; j++) {
        const int col = 8 * j + 2 * tg;
        *(float2*)(Cg + (size_t)rowA * DD + col) =
            make_float2(__uint_as_float(f2tf32(o[j][0] * invA)),
                        __uint_as_float(f2tf32(o[j][1] * invA)));
        *(float2*)(Cg + (size_t)(rowA + 8) * DD + col) =
            make_float2(__uint_as_float(f2tf32(o[j][2] * invB)),
                        __uint_as_float(f2tf32(o[j][3] * invB)));
    }
#undef ATT_LOAD_STAGE
}

// ---------------- launch ------------------------------------------------------
extern "C" void kernel_launch(void* const* d_in, const int* /*in_sizes*/, int /*n_in*/,
                              void* d_out, int /*out_size*/)
{
    const float* q  = (const float*)d_in[0];
    const float* k  = (const float*)d_in[1];
    const float* v  = (const float*)d_in[2];
    const float* Wq = (const float*)d_in[3];
    const float* bq = (const float*)d_in[4];
    const float* Wk = (const float*)d_in[5];
    const float* bk = (const float*)d_in[6];
    const float* Wv = (const float*)d_in[7];
    const float* bv = (const float*)d_in[8];
    const float* Wo = (const float*)d_in[9];
    const float* bo = (const float*)d_in[10];
    float* out = (float*)d_out;

    float *Qh, *Kh, *Vh, *Ctx;
    cudaGetSymbolAddress((void**)&Qh,  g_Qh);
    cudaGetSymbolAddress((void**)&Kh,  g_Kh);
    cudaGetSymbolAddress((void**)&Vh,  g_Vh);
    cudaGetSymbolAddress((void**)&Ctx, g_Ctx);

    cudaFuncSetAttribute(gemm_bias_kernel<true, true>,
                         cudaFuncAttributeMaxDynamicSharedMemorySize, GEMM_SMEM_BYTES);
    cudaFuncSetAttribute(gemm_bias_kernel<false, false>,
                         cudaFuncAttributeMaxDynamicSharedMemorySize, GEMM_SMEM_BYTES);
    cudaFuncSetAttribute(attn_kernel,
                         cudaFuncAttributeMaxDynamicSharedMemorySize, ATT_SMEM_BYTES);

    const dim3 gg(DD / GBN, MM / GBM);   // (8, 32)

    // projections: outputs pre-rounded to tf32 for the attention kernel
    gemm_bias_kernel<true, true><<<gg, 256, GEMM_SMEM_BYTES>>>(q, Wq, bq, Qh);
    gemm_bias_kernel<true, true><<<gg, 256, GEMM_SMEM_BYTES>>>(k, Wk, bk, Kh);
    gemm_bias_kernel<true, true><<<gg, 256, GEMM_SMEM_BYTES>>>(v, Wv, bv, Vh);

    attn_kernel<<<dim3(SS / 64, BB * HH), 128, ATT_SMEM_BYTES>>>(Qh, Kh, Vh, Ctx);

    // output projection: Ctx already tf32 (skip A cvt), full-precision store
    gemm_bias_kernel<false, false><<<gg, 256, GEMM_SMEM_BYTES>>>(Ctx, Wo, bo, out);
}

// round 5
// speedup vs baseline: 3.7105x; 1.0083x over previous
#include <cuda_runtime.h>
#include <math.h>
#include <stdint.h>

// Problem shape (fixed by the reference)
#define BB   2
#define SS   2048
#define DD   1024
#define HH   16
#define DKK  64
#define MM   (BB * SS)   // 4096 rows

// ---------------- scratch (device globals; no allocation allowed) -------------
__device__ float g_Qh[MM * DD];
__device__ float g_Kh[MM * DD];
__device__ float g_Vh[MM * DD];
__device__ float g_Ctx[MM * DD];
// tf32-pre-rounded operands (so GEMMs run cvt-free)
__device__ float g_Xq[MM * DD];
__device__ float g_Xk[MM * DD];
__device__ float g_Xv[MM * DD];
__device__ float g_Wqr[DD * DD];
__device__ float g_Wkr[DD * DD];
__device__ float g_Wvr[DD * DD];
__device__ float g_Wor[DD * DD];

// ---------------- PTX helpers -------------------------------------------------
__device__ __forceinline__ uint32_t f2tf32(float x) {
    uint32_t r;
    asm("cvt.rna.tf32.f32 %0, %1;\n" : "=r"(r) : "f"(x));
    return r;
}

// D(16x8) += A(16x8,tf32,row) * B(8x8,tf32,col)
__device__ __forceinline__ void mma_tf32(float c[4], const uint32_t a[4], const uint32_t b[2]) {
    asm volatile(
        "mma.sync.aligned.m16n8k8.row.col.f32.tf32.tf32.f32 "
        "{%0,%1,%2,%3}, {%4,%5,%6,%7}, {%8,%9}, {%0,%1,%2,%3};\n"
        : "+f"(c[0]), "+f"(c[1]), "+f"(c[2]), "+f"(c[3])
        : "r"(a[0]), "r"(a[1]), "r"(a[2]), "r"(a[3]), "r"(b[0]), "r"(b[1]));
}

__device__ __forceinline__ void cp_async16(void* smem, const void* gmem) {
    uint32_t s = (uint32_t)__cvta_generic_to_shared(smem);
    asm volatile("cp.async.cg.shared.global [%0], [%1], 16;\n" :: "r"(s), "l"(gmem));
}
__device__ __forceinline__ void cp_commit()  { asm volatile("cp.async.commit_group;\n"); }
__device__ __forceinline__ void cp_wait0()   { asm volatile("cp.async.wait_group 0;\n"); }

// ---------------- elementwise tf32 pre-round ----------------------------------
__global__ void round_tf32_kernel(const float* __restrict__ x, float* __restrict__ y)
{
    const int i = blockIdx.x * blockDim.x + threadIdx.x;   // float4 index
    float4 v = ((const float4*)x)[i];
    v.x = __uint_as_float(f2tf32(v.x));
    v.y = __uint_as_float(f2tf32(v.y));
    v.z = __uint_as_float(f2tf32(v.z));
    v.w = __uint_as_float(f2tf32(v.w));
    ((float4*)y)[i] = v;
}

// ---------------- GEMM: Y[m,n] = sum_k X[m,k]*W[n,k] + bias[n] ----------------
// Raw mma m16n8k8 TF32. Operands are PRE-ROUNDED to tf32 -> no cvt in the loop.
// Block 128x128, GBK=32, 2-stage cp.async pipeline.
// 8 warps in 2(m) x 4(n); warp tile 64x32 -> c[4 mtiles][4 ntiles][4].
// RND: round the output to tf32 bits before storing (for attention consumers).
#define GBM 128
#define GBN 128
#define GBK 32
#define GLD 36   // 32+4 pad: row stride = 36 words == 4 mod 32 -> conflict-free frag loads
#define GEMM_SMEM_BYTES (2 * (GBM + GBN) * GLD * 4)

template<bool RND>
__global__ __launch_bounds__(256, 2) void gemm_bias_kernel(
    const float* __restrict__ X, const float* __restrict__ W,
    const float* __restrict__ bias, float* __restrict__ Y)
{
    extern __shared__ __align__(16) float sm[];
    float* As = sm;                       // [2][128][GLD]
    float* Bs = sm + 2 * GBM * GLD;       // [2][128][GLD]

    const int tid  = threadIdx.x;
    const int warp = tid >> 5, lane = tid & 31;
    const int g = lane >> 2, tg = lane & 3;
    const int wm = warp >> 2, wn = warp & 3;
    const int m0 = blockIdx.y * GBM, n0 = blockIdx.x * GBN;

    float c[4][4][4];
#pragma unroll
    for (int i = 0; i < 4; i++)
#pragma unroll
        for (int j = 0; j < 4; j++)
#pragma unroll
            for (int t = 0; t < 4; t++) c[i][j][t] = 0.f;

    const float* Xg = X + (size_t)m0 * DD;
    const float* Wg = W + (size_t)n0 * DD;

#define GEMM_LOAD_STAGE(s, k0)                                                        \
    do {                                                                              \
        _Pragma("unroll")                                                             \
        for (int i = tid; i < GBM * (GBK / 4); i += 256) {                            \
            int r = i >> 3, c4 = i & 7;                                               \
            cp_async16(&As[(s) * GBM * GLD + r * GLD + c4 * 4],                       \
                       Xg + (size_t)r * DD + (k0) + c4 * 4);                          \
            cp_async16(&Bs[(s) * GBN * GLD + r * GLD + c4 * 4],                       \
                       Wg + (size_t)r * DD + (k0) + c4 * 4);                          \
        }                                                                             \
    } while (0)

    GEMM_LOAD_STAGE(0, 0);
    cp_commit(); cp_wait0();
    __syncthreads();

    const int nK = DD / GBK;   // 32
    for (int kt = 0; kt < nK; kt++) {
        const int s = kt & 1;
        if (kt + 1 < nK) { GEMM_LOAD_STAGE(s ^ 1, (kt + 1) * GBK); cp_commit(); }

        const float* A = As + s * GBM * GLD;
        const float* B = Bs + s * GBN * GLD;
#pragma unroll
        for (int kk = 0; kk < GBK; kk += 8) {
            uint32_t a[4][4], b[4][2];
#pragma unroll
            for (int mi = 0; mi < 4; mi++) {
                int r = (wm * 64 + mi * 16 + g) * GLD;
                a[mi][0] = __float_as_uint(A[r + kk + tg]);
                a[mi][1] = __float_as_uint(A[r + 8 * GLD + kk + tg]);
                a[mi][2] = __float_as_uint(A[r + kk + tg + 4]);
                a[mi][3] = __float_as_uint(A[r + 8 * GLD + kk + tg + 4]);
            }
#pragma unroll
            for (int nj = 0; nj < 4; nj++) {
                int rn = (wn * 32 + nj * 8 + g) * GLD;
                b[nj][0] = __float_as_uint(B[rn + kk + tg]);
                b[nj][1] = __float_as_uint(B[rn + kk + tg + 4]);
            }
#pragma unroll
            for (int mi = 0; mi < 4; mi++)
#pragma unroll
                for (int nj = 0; nj < 4; nj++)
                    mma_tf32(c[mi][nj], a[mi], b[nj]);
        }
        cp_wait0();
        __syncthreads();
    }

    // epilogue: + bias, (optional tf32 pre-round), store
#pragma unroll
    for (int nj = 0; nj < 4; nj++) {
        const int coln = n0 + wn * 32 + nj * 8 + 2 * tg;
        const float2 bb = *(const float2*)(bias + coln);
#pragma unroll
        for (int mi = 0; mi < 4; mi++) {
            const int row = m0 + wm * 64 + mi * 16 + g;
            float y00 = c[mi][nj][0] + bb.x, y01 = c[mi][nj][1] + bb.y;
            float y10 = c[mi][nj][2] + bb.x, y11 = c[mi][nj][3] + bb.y;
            if (RND) {
                y00 = __uint_as_float(f2tf32(y00));
                y01 = __uint_as_float(f2tf32(y01));
                y10 = __uint_as_float(f2tf32(y10));
                y11 = __uint_as_float(f2tf32(y11));
            }
            *(float2*)(Y + (size_t)row * DD + coln)       = make_float2(y00, y01);
            *(float2*)(Y + (size_t)(row + 8) * DD + coln) = make_float2(y10, y11);
        }
    }
#undef GEMM_LOAD_STAGE
}

// ---------------- flash attention: warp M-tile 32, register softmax -----------
// BM=128 q rows per block, 4 warps (32 rows each = 2 A-tiles). Each K/V
// B-fragment load now feeds TWO mma -> LDS per mma halved vs warp-M=16.
// Inputs pre-rounded tf32 bits; 1/8 scale folded into Q (exact).
#define KLD 68   // k-major tiles: stride == 4 mod 32 -> conflict-free frag loads
#define VLD 72   // V (n-major access): stride == 8 mod 32 -> conflict-free
#define ATT_SMEM_FLOATS (2 * 64 * KLD + 2 * 64 * VLD + 128 * KLD)
#define ATT_SMEM_BYTES  (ATT_SMEM_FLOATS * 4)

__global__ __launch_bounds__(128, 2) void attn_kernel(
    const float* __restrict__ Qh, const float* __restrict__ Kh,
    const float* __restrict__ Vh, float* __restrict__ Ctx)
{
    extern __shared__ __align__(16) float sm[];
    float* Ks = sm;                          // [2][64][KLD]
    float* Vs = Ks + 2 * 64 * KLD;           // [2][64][VLD]
    float* Ss = Vs + 2 * 64 * VLD;           // [128][KLD]: 4 warp slabs of 32 rows

    const int tid  = threadIdx.x;
    const int warp = tid >> 5, lane = tid & 31;
    const int g = lane >> 2, tg = lane & 3;
    const int qt = blockIdx.x;          // 0..15 (128 q rows each)
    const int bh = blockIdx.y;          // 0..31
    const int b  = bh >> 4;
    const int h  = bh & 15;

    const size_t rowQ0 = (size_t)(b * SS + qt * 128);
    const size_t colH  = (size_t)h * DKK;
    const float* Qg  = Qh + rowQ0 * DD + colH;
    const float* Kg0 = Kh + (size_t)(b * SS) * DD + colH;
    const float* Vg0 = Vh + (size_t)(b * SS) * DD + colH;

#define ATT_LOAD_STAGE(s, kt)                                                          \
    do {                                                                               \
        const float* Kg = Kg0 + (size_t)((kt) * 64) * DD;                              \
        const float* Vg = Vg0 + (size_t)((kt) * 64) * DD;                              \
        _Pragma("unroll")                                                              \
        for (int i = tid; i < 64 * 16; i += 128) {                                     \
            int r = i >> 4, c4 = i & 15;                                               \
            cp_async16(&Ks[(s) * 64 * KLD + r * KLD + c4 * 4],                         \
                       Kg + (size_t)r * DD + c4 * 4);                                  \
            cp_async16(&Vs[(s) * 64 * VLD + r * VLD + c4 * 4],                         \
                       Vg + (size_t)r * DD + c4 * 4);                                  \
        }                                                                              \
    } while (0)

    ATT_LOAD_STAGE(0, 0);
    cp_commit();

    // ---- stage this warp's 32 Q rows into its slab; build 2 A-tiles ----
    float* Sw = Ss + (warp * 32) * KLD;   // warp slab: rows 0..31
    {
        const float* Qw = Qg + (size_t)(warp * 32) * DD;
#pragma unroll
        for (int i = lane; i < 32 * 16; i += 32) {
            int r = i >> 4, c4 = i & 15;
            *(float4*)&Sw[r * KLD + c4 * 4] = *(const float4*)(Qw + (size_t)r * DD + c4 * 4);
        }
    }
    __syncwarp();

    uint32_t aq0[8][4], aq1[8][4];
    {
        const float scale = 0.125f;   // exact power of two: tf32 stays tf32
        const int r0 = g * KLD, r1 = (g + 8) * KLD;
        const int r2 = (16 + g) * KLD, r3 = (24 + g) * KLD;
#pragma unroll
        for (int kk = 0; kk < 8; kk++) {
            aq0[kk][0] = __float_as_uint(Sw[r0 + 8 * kk + tg] * scale);
            aq0[kk][1] = __float_as_uint(Sw[r1 + 8 * kk + tg] * scale);
            aq0[kk][2] = __float_as_uint(Sw[r0 + 8 * kk + tg + 4] * scale);
            aq0[kk][3] = __float_as_uint(Sw[r1 + 8 * kk + tg + 4] * scale);
            aq1[kk][0] = __float_as_uint(Sw[r2 + 8 * kk + tg] * scale);
            aq1[kk][1] = __float_as_uint(Sw[r3 + 8 * kk + tg] * scale);
            aq1[kk][2] = __float_as_uint(Sw[r2 + 8 * kk + tg + 4] * scale);
            aq1[kk][3] = __float_as_uint(Sw[r3 + 8 * kk + tg + 4] * scale);
        }
    }
    __syncwarp();   // slab now free for P

    float o0[8][4], o1[8][4];
#pragma unroll
    for (int j = 0; j < 8; j++)
#pragma unroll
        for (int t = 0; t < 4; t++) { o0[j][t] = 0.f; o1[j][t] = 0.f; }
    float mA0 = -INFINITY, mB0 = -INFINITY, lA0 = 0.f, lB0 = 0.f;
    float mA1 = -INFINITY, mB1 = -INFINITY, lA1 = 0.f, lB1 = 0.f;

    cp_wait0();
    __syncthreads();

    for (int kt = 0; kt < SS / 64; kt++) {
        const int s = kt & 1;
        if (kt + 1 < SS / 64) { ATT_LOAD_STAGE(s ^ 1, kt + 1); cp_commit(); }

        const float* K = Ks + s * 64 * KLD;
        const float* V = Vs + s * 64 * VLD;

        // ---- S = (Q/8) K^T : 32 x 64 per warp, K fragment reused for 2 tiles ----
        float sc0[8][4], sc1[8][4];
#pragma unroll
        for (int j = 0; j < 8; j++)
#pragma unroll
            for (int t = 0; t < 4; t++) { sc0[j][t] = 0.f; sc1[j][t] = 0.f; }

#pragma unroll
        for (int kk = 0; kk < 8; kk++) {
#pragma unroll
            for (int j = 0; j < 8; j++) {
                uint32_t bfr[2];
                const int rn = (8 * j + g) * KLD + 8 * kk + tg;
                bfr[0] = __float_as_uint(K[rn]);
                bfr[1] = __float_as_uint(K[rn + 4]);
                mma_tf32(sc0[j], aq0[kk], bfr);
                mma_tf32(sc1[j], aq1[kk], bfr);
            }
        }

        // ---- online softmax in registers (4 rows per thread) ----
        float mxA0 = -INFINITY, mxB0 = -INFINITY, mxA1 = -INFINITY, mxB1 = -INFINITY;
#pragma unroll
        for (int j = 0; j < 8; j++) {
            mxA0 = fmaxf(mxA0, fmaxf(sc0[j][0], sc0[j][1]));
            mxB0 = fmaxf(mxB0, fmaxf(sc0[j][2], sc0[j][3]));
            mxA1 = fmaxf(mxA1, fmaxf(sc1[j][0], sc1[j][1]));
            mxB1 = fmaxf(mxB1, fmaxf(sc1[j][2], sc1[j][3]));
        }
#pragma unroll
        for (int off = 1; off <= 2; off <<= 1) {
            mxA0 = fmaxf(mxA0, __shfl_xor_sync(0xffffffffu, mxA0, off));
            mxB0 = fmaxf(mxB0, __shfl_xor_sync(0xffffffffu, mxB0, off));
            mxA1 = fmaxf(mxA1, __shfl_xor_sync(0xffffffffu, mxA1, off));
            mxB1 = fmaxf(mxB1, __shfl_xor_sync(0xffffffffu, mxB1, off));
        }

        const float mA0n = fmaxf(mA0, mxA0), mB0n = fmaxf(mB0, mxB0);
        const float mA1n = fmaxf(mA1, mxA1), mB1n = fmaxf(mB1, mxB1);
        const float aA0 = __expf(mA0 - mA0n), aB0 = __expf(mB0 - mB0n);
        const float aA1 = __expf(mA1 - mA1n), aB1 = __expf(mB1 - mB1n);

        float sA0 = 0.f, sB0 = 0.f, sA1 = 0.f, sB1 = 0.f;
#pragma unroll
        for (int j = 0; j < 8; j++) {
            sc0[j][0] = __expf(sc0[j][0] - mA0n);
            sc0[j][1] = __expf(sc0[j][1] - mA0n);
            sc0[j][2] = __expf(sc0[j][2] - mB0n);
            sc0[j][3] = __expf(sc0[j][3] - mB0n);
            sc1[j][0] = __expf(sc1[j][0] - mA1n);
            sc1[j][1] = __expf(sc1[j][1] - mA1n);
            sc1[j][2] = __expf(sc1[j][2] - mB1n);
            sc1[j][3] = __expf(sc1[j][3] - mB1n);
            sA0 += sc0[j][0] + sc0[j][1];
            sB0 += sc0[j][2] + sc0[j][3];
            sA1 += sc1[j][0] + sc1[j][1];
            sB1 += sc1[j][2] + sc1[j][3];
        }
#pragma unroll
        for (int off = 1; off <= 2; off <<= 1) {
            sA0 += __shfl_xor_sync(0xffffffffu, sA0, off);
            sB0 += __shfl_xor_sync(0xffffffffu, sB0, off);
            sA1 += __shfl_xor_sync(0xffffffffu, sA1, off);
            sB1 += __shfl_xor_sync(0xffffffffu, sB1, off);
        }

        lA0 = lA0 * aA0 + sA0;  mA0 = mA0n;
        lB0 = lB0 * aB0 + sB0;  mB0 = mB0n;
        lA1 = lA1 * aA1 + sA1;  mA1 = mA1n;
        lB1 = lB1 * aB1 + sB1;  mB1 = mB1n;

#pragma unroll
        for (int j = 0; j < 8; j++) {
            o0[j][0] *= aA0; o0[j][1] *= aA0; o0[j][2] *= aB0; o0[j][3] *= aB0;
            o1[j][0] *= aA1; o1[j][1] *= aA1; o1[j][2] *= aB1; o1[j][3] *= aB1;
        }

        // ---- P -> slab (pre-rounded tf32), then O += P V (V frag reused 2x) ----
#pragma unroll
        for (int j = 0; j < 8; j++) {
            *(float2*)&Sw[g * KLD + 8 * j + 2 * tg] =
                make_float2(__uint_as_float(f2tf32(sc0[j][0])),
                            __uint_as_float(f2tf32(sc0[j][1])));
            *(float2*)&Sw[(g + 8) * KLD + 8 * j + 2 * tg] =
                make_float2(__uint_as_float(f2tf32(sc0[j][2])),
                            __uint_as_float(f2tf32(sc0[j][3])));
            *(float2*)&Sw[(16 + g) * KLD + 8 * j + 2 * tg] =
                make_float2(__uint_as_float(f2tf32(sc1[j][0])),
                            __uint_as_float(f2tf32(sc1[j][1])));
            *(float2*)&Sw[(24 + g) * KLD + 8 * j + 2 * tg] =
                make_float2(__uint_as_float(f2tf32(sc1[j][2])),
                            __uint_as_float(f2tf32(sc1[j][3])));
        }
        __syncwarp();

#pragma unroll
        for (int kk = 0; kk < 8; kk++) {
            uint32_t pa0[4], pa1[4];
            pa0[0] = __float_as_uint(Sw[g * KLD + 8 * kk + tg]);
            pa0[1] = __float_as_uint(Sw[(g + 8) * KLD + 8 * kk + tg]);
            pa0[2] = __float_as_uint(Sw[g * KLD + 8 * kk + tg + 4]);
            pa0[3] = __float_as_uint(Sw[(g + 8) * KLD + 8 * kk + tg + 4]);
            pa1[0] = __float_as_uint(Sw[(16 + g) * KLD + 8 * kk + tg]);
            pa1[1] = __float_as_uint(Sw[(24 + g) * KLD + 8 * kk + tg]);
            pa1[2] = __float_as_uint(Sw[(16 + g) * KLD + 8 * kk + tg + 4]);
            pa1[3] = __float_as_uint(Sw[(24 + g) * KLD + 8 * kk + tg + 4]);
#pragma unroll
            for (int j = 0; j < 8; j++) {
                uint32_t bfr[2];
                const int rv = (8 * kk + tg) * VLD + 8 * j + g;
                bfr[0] = __float_as_uint(V[rv]);
                bfr[1] = __float_as_uint(V[rv + 4 * VLD]);
                mma_tf32(o0[j], pa0, bfr);
                mma_tf32(o1[j], pa1, bfr);
            }
        }

        cp_wait0();
        __syncthreads();   // guard K/V buffer reuse
    }

    // ---- epilogue: ctx = O / l, pre-rounded to tf32 for the final GEMM ----
    const float iA0 = 1.f / lA0, iB0 = 1.f / lB0;
    const float iA1 = 1.f / lA1, iB1 = 1.f / lB1;
    float* Cg = Ctx + (rowQ0 + warp * 32) * DD + colH;
#pragma unroll
    for (int j = 0; j < 8; j++) {
        const int col = 8 * j + 2 * tg;
        *(float2*)(Cg + (size_t)g * DD + col) =
            make_float2(__uint_as_float(f2tf32(o0[j][0] * iA0)),
                        __uint_as_float(f2tf32(o0[j][1] * iA0)));
        *(float2*)(Cg + (size_t)(g + 8) * DD + col) =
            make_float2(__uint_as_float(f2tf32(o0[j][2] * iB0)),
                        __uint_as_float(f2tf32(o0[j][3] * iB0)));
        *(float2*)(Cg + (size_t)(16 + g) * DD + col) =
            make_float2(__uint_as_float(f2tf32(o1[j][0] * iA1)),
                        __uint_as_float(f2tf32(o1[j][1] * iA1)));
        *(float2*)(Cg + (size_t)(24 + g) * DD + col) =
            make_float2(__uint_as_float(f2tf32(o1[j][2] * iB1)),
                        __uint_as_float(f2tf32(o1[j][3] * iB1)));
    }
#undef ATT_LOAD_STAGE
}

// ---------------- launch ------------------------------------------------------
extern "C" void kernel_launch(void* const* d_in, const int* /*in_sizes*/, int /*n_in*/,
                              void* d_out, int /*out_size*/)
{
    const float* q  = (const float*)d_in[0];
    const float* k  = (const float*)d_in[1];
    const float* v  = (const float*)d_in[2];
    const float* Wq = (const float*)d_in[3];
    const float* bq = (const float*)d_in[4];
    const float* Wk = (const float*)d_in[5];
    const float* bk = (const float*)d_in[6];
    const float* Wv = (const float*)d_in[7];
    const float* bv = (const float*)d_in[8];
    const float* Wo = (const float*)d_in[9];
    const float* bo = (const float*)d_in[10];
    float* out = (float*)d_out;

    float *Qh, *Kh, *Vh, *Ctx, *Xq, *Xk, *Xv, *Wqr, *Wkr, *Wvr, *Wor;
    cudaGetSymbolAddress((void**)&Qh,  g_Qh);
    cudaGetSymbolAddress((void**)&Kh,  g_Kh);
    cudaGetSymbolAddress((void**)&Vh,  g_Vh);
    cudaGetSymbolAddress((void**)&Ctx, g_Ctx);
    cudaGetSymbolAddress((void**)&Xq,  g_Xq);
    cudaGetSymbolAddress((void**)&Xk,  g_Xk);
    cudaGetSymbolAddress((void**)&Xv,  g_Xv);
    cudaGetSymbolAddress((void**)&Wqr, g_Wqr);
    cudaGetSymbolAddress((void**)&Wkr, g_Wkr);
    cudaGetSymbolAddress((void**)&Wvr, g_Wvr);
    cudaGetSymbolAddress((void**)&Wor, g_Wor);

    cudaFuncSetAttribute(gemm_bias_kernel<true>,
                         cudaFuncAttributeMaxDynamicSharedMemorySize, GEMM_SMEM_BYTES);
    cudaFuncSetAttribute(gemm_bias_kernel<false>,
                         cudaFuncAttributeMaxDynamicSharedMemorySize, GEMM_SMEM_BYTES);
    cudaFuncSetAttribute(attn_kernel,
                         cudaFuncAttributeMaxDynamicSharedMemorySize, ATT_SMEM_BYTES);

    // pre-round every GEMM operand to tf32 bits (cvt(cvt(x)) == cvt(x))
    const int rbX = (MM * DD / 4) / 256;   // 4096 blocks
    const int rbW = (DD * DD / 4) / 256;   // 1024 blocks
    round_tf32_kernel<<<rbX, 256>>>(q,  Xq);
    round_tf32_kernel<<<rbX, 256>>>(k,  Xk);
    round_tf32_kernel<<<rbX, 256>>>(v,  Xv);
    round_tf32_kernel<<<rbW, 256>>>(Wq, Wqr);
    round_tf32_kernel<<<rbW, 256>>>(Wk, Wkr);
    round_tf32_kernel<<<rbW, 256>>>(Wv, Wvr);
    round_tf32_kernel<<<rbW, 256>>>(Wo, Wor);

    const dim3 gg(DD / GBN, MM / GBM);   // (8, 32)

    // projections: outputs pre-rounded to tf32 for the attention kernel
    gemm_bias_kernel<true><<<gg, 256, GEMM_SMEM_BYTES>>>(Xq, Wqr, bq, Qh);
    gemm_bias_kernel<true><<<gg, 256, GEMM_SMEM_BYTES>>>(Xk, Wkr, bk, Kh);
    gemm_bias_kernel<true><<<gg, 256, GEMM_SMEM_BYTES>>>(Xv, Wvr, bv, Vh);

    attn_kernel<<<dim3(SS / 128, BB * HH), 128, ATT_SMEM_BYTES>>>(Qh, Kh, Vh, Ctx);

    // output projection: Ctx already tf32, full-precision store
    gemm_bias_kernel<false><<<gg, 256, GEMM_SMEM_BYTES>>>(Ctx, Wor, bo, out);
}

// round 6
// speedup vs baseline: 3.7109x; 1.0001x over previous
#include <cuda_runtime.h>
#include <math.h>
#include <stdint.h>

// Problem shape (fixed by the reference)
#define BB   2
#define SS   2048
#define DD   1024
#define HH   16
#define DKK  64
#define MM   (BB * SS)   // 4096 rows

// ---------------- scratch (device globals; no allocation allowed) -------------
__device__ float g_Qh[MM * DD];
__device__ float g_Kh[MM * DD];
__device__ float g_Vh[MM * DD];
__device__ float g_Ctx[MM * DD];
// tf32-pre-rounded operands (so GEMMs run cvt-free)
__device__ float g_Xq[MM * DD];
__device__ float g_Xk[MM * DD];
__device__ float g_Xv[MM * DD];
__device__ float g_Wqr[DD * DD];
__device__ float g_Wkr[DD * DD];
__device__ float g_Wvr[DD * DD];
__device__ float g_Wor[DD * DD];

// ---------------- PTX helpers -------------------------------------------------
__device__ __forceinline__ uint32_t f2tf32(float x) {
    uint32_t r;
    asm("cvt.rna.tf32.f32 %0, %1;\n" : "=r"(r) : "f"(x));
    return r;
}

// D(16x8) += A(16x8,tf32,row) * B(8x8,tf32,col)
__device__ __forceinline__ void mma_tf32(float c[4], const uint32_t a[4], const uint32_t b[2]) {
    asm volatile(
        "mma.sync.aligned.m16n8k8.row.col.f32.tf32.tf32.f32 "
        "{%0,%1,%2,%3}, {%4,%5,%6,%7}, {%8,%9}, {%0,%1,%2,%3};\n"
        : "+f"(c[0]), "+f"(c[1]), "+f"(c[2]), "+f"(c[3])
        : "r"(a[0]), "r"(a[1]), "r"(a[2]), "r"(a[3]), "r"(b[0]), "r"(b[1]));
}

__device__ __forceinline__ void cp_async16(void* smem, const void* gmem) {
    uint32_t s = (uint32_t)__cvta_generic_to_shared(smem);
    asm volatile("cp.async.cg.shared.global [%0], [%1], 16;\n" :: "r"(s), "l"(gmem));
}
__device__ __forceinline__ void cp_commit()  { asm volatile("cp.async.commit_group;\n"); }
__device__ __forceinline__ void cp_wait0()   { asm volatile("cp.async.wait_group 0;\n"); }

// ---------------- elementwise tf32 pre-round ----------------------------------
__global__ void round_tf32_kernel(const float* __restrict__ x, float* __restrict__ y)
{
    const int i = blockIdx.x * blockDim.x + threadIdx.x;   // float4 index
    float4 v = ((const float4*)x)[i];
    v.x = __uint_as_float(f2tf32(v.x));
    v.y = __uint_as_float(f2tf32(v.y));
    v.z = __uint_as_float(f2tf32(v.z));
    v.w = __uint_as_float(f2tf32(v.w));
    ((float4*)y)[i] = v;
}

// ---------------- GEMM: Y[m,n] = sum_k X[m,k]*W[n,k] + bias[n] ----------------
// Raw mma m16n8k8 TF32. Operands are PRE-ROUNDED to tf32 -> no cvt in the loop.
// Block 128x128, GBK=32, 2-stage cp.async pipeline.
// 8 warps in 2(m) x 4(n); warp tile 64x32 -> c[4 mtiles][4 ntiles][4].
// RND: round the output to tf32 bits before storing (for attention consumers).
#define GBM 128
#define GBN 128
#define GBK 32
#define GLD 36   // 32+4 pad: row stride = 36 words == 4 mod 32 -> conflict-free frag loads
#define GEMM_SMEM_BYTES (2 * (GBM + GBN) * GLD * 4)

template<bool RND>
__global__ __launch_bounds__(256, 2) void gemm_bias_kernel(
    const float* __restrict__ X, const float* __restrict__ W,
    const float* __restrict__ bias, float* __restrict__ Y)
{
    extern __shared__ __align__(16) float sm[];
    float* As = sm;                       // [2][128][GLD]
    float* Bs = sm + 2 * GBM * GLD;       // [2][128][GLD]

    const int tid  = threadIdx.x;
    const int warp = tid >> 5, lane = tid & 31;
    const int g = lane >> 2, tg = lane & 3;
    const int wm = warp >> 2, wn = warp & 3;
    const int m0 = blockIdx.y * GBM, n0 = blockIdx.x * GBN;

    float c[4][4][4];
#pragma unroll
    for (int i = 0; i < 4; i++)
#pragma unroll
        for (int j = 0; j < 4; j++)
#pragma unroll
            for (int t = 0; t < 4; t++) c[i][j][t] = 0.f;

    const float* Xg = X + (size_t)m0 * DD;
    const float* Wg = W + (size_t)n0 * DD;

#define GEMM_LOAD_STAGE(s, k0)                                                        \
    do {                                                                              \
        _Pragma("unroll")                                                             \
        for (int i = tid; i < GBM * (GBK / 4); i += 256) {                            \
            int r = i >> 3, c4 = i & 7;                                               \
            cp_async16(&As[(s) * GBM * GLD + r * GLD + c4 * 4],                       \
                       Xg + (size_t)r * DD + (k0) + c4 * 4);                          \
            cp_async16(&Bs[(s) * GBN * GLD + r * GLD + c4 * 4],                       \
                       Wg + (size_t)r * DD + (k0) + c4 * 4);                          \
        }                                                                             \
    } while (0)

    GEMM_LOAD_STAGE(0, 0);
    cp_commit(); cp_wait0();
    __syncthreads();

    const int nK = DD / GBK;   // 32
    for (int kt = 0; kt < nK; kt++) {
        const int s = kt & 1;
        if (kt + 1 < nK) { GEMM_LOAD_STAGE(s ^ 1, (kt + 1) * GBK); cp_commit(); }

        const float* A = As + s * GBM * GLD;
        const float* B = Bs + s * GBN * GLD;
#pragma unroll
        for (int kk = 0; kk < GBK; kk += 8) {
            uint32_t a[4][4], b[4][2];
#pragma unroll
            for (int mi = 0; mi < 4; mi++) {
                int r = (wm * 64 + mi * 16 + g) * GLD;
                a[mi][0] = __float_as_uint(A[r + kk + tg]);
                a[mi][1] = __float_as_uint(A[r + 8 * GLD + kk + tg]);
                a[mi][2] = __float_as_uint(A[r + kk + tg + 4]);
                a[mi][3] = __float_as_uint(A[r + 8 * GLD + kk + tg + 4]);
            }
#pragma unroll
            for (int nj = 0; nj < 4; nj++) {
                int rn = (wn * 32 + nj * 8 + g) * GLD;
                b[nj][0] = __float_as_uint(B[rn + kk + tg]);
                b[nj][1] = __float_as_uint(B[rn + kk + tg + 4]);
            }
#pragma unroll
            for (int mi = 0; mi < 4; mi++)
#pragma unroll
                for (int nj = 0; nj < 4; nj++)
                    mma_tf32(c[mi][nj], a[mi], b[nj]);
        }
        cp_wait0();
        __syncthreads();
    }

    // epilogue: + bias, (optional tf32 pre-round), store
#pragma unroll
    for (int nj = 0; nj < 4; nj++) {
        const int coln = n0 + wn * 32 + nj * 8 + 2 * tg;
        const float2 bb = *(const float2*)(bias + coln);
#pragma unroll
        for (int mi = 0; mi < 4; mi++) {
            const int row = m0 + wm * 64 + mi * 16 + g;
            float y00 = c[mi][nj][0] + bb.x, y01 = c[mi][nj][1] + bb.y;
            float y10 = c[mi][nj][2] + bb.x, y11 = c[mi][nj][3] + bb.y;
            if (RND) {
                y00 = __uint_as_float(f2tf32(y00));
                y01 = __uint_as_float(f2tf32(y01));
                y10 = __uint_as_float(f2tf32(y10));
                y11 = __uint_as_float(f2tf32(y11));
            }
            *(float2*)(Y + (size_t)row * DD + coln)       = make_float2(y00, y01);
            *(float2*)(Y + (size_t)(row + 8) * DD + coln) = make_float2(y10, y11);
        }
    }
#undef GEMM_LOAD_STAGE
}

// ---------------- flash attention: warp M-tile 32, register softmax -----------
// BM=128 q rows per block, 4 warps (32 rows each = 2 A-tiles). Each K/V
// B-fragment load now feeds TWO mma -> LDS per mma halved vs warp-M=16.
// Inputs pre-rounded tf32 bits; 1/8 scale folded into Q (exact).
#define KLD 68   // k-major tiles: stride == 4 mod 32 -> conflict-free frag loads
#define VLD 72   // V (n-major access): stride == 8 mod 32 -> conflict-free
#define ATT_SMEM_FLOATS (2 * 64 * KLD + 2 * 64 * VLD + 128 * KLD)
#define ATT_SMEM_BYTES  (ATT_SMEM_FLOATS * 4)

__global__ __launch_bounds__(128, 2) void attn_kernel(
    const float* __restrict__ Qh, const float* __restrict__ Kh,
    const float* __restrict__ Vh, float* __restrict__ Ctx)
{
    extern __shared__ __align__(16) float sm[];
    float* Ks = sm;                          // [2][64][KLD]
    float* Vs = Ks + 2 * 64 * KLD;           // [2][64][VLD]
    float* Ss = Vs + 2 * 64 * VLD;           // [128][KLD]: 4 warp slabs of 32 rows

    const int tid  = threadIdx.x;
    const int warp = tid >> 5, lane = tid & 31;
    const int g = lane >> 2, tg = lane & 3;
    const int qt = blockIdx.x;          // 0..15 (128 q rows each)
    const int bh = blockIdx.y;          // 0..31
    const int b  = bh >> 4;
    const int h  = bh & 15;

    const size_t rowQ0 = (size_t)(b * SS + qt * 128);
    const size_t colH  = (size_t)h * DKK;
    const float* Qg  = Qh + rowQ0 * DD + colH;
    const float* Kg0 = Kh + (size_t)(b * SS) * DD + colH;
    const float* Vg0 = Vh + (size_t)(b * SS) * DD + colH;

#define ATT_LOAD_STAGE(s, kt)                                                          \
    do {                                                                               \
        const float* Kg = Kg0 + (size_t)((kt) * 64) * DD;                              \
        const float* Vg = Vg0 + (size_t)((kt) * 64) * DD;                              \
        _Pragma("unroll")                                                              \
        for (int i = tid; i < 64 * 16; i += 128) {                                     \
            int r = i >> 4, c4 = i & 15;                                               \
            cp_async16(&Ks[(s) * 64 * KLD + r * KLD + c4 * 4],                         \
                       Kg + (size_t)r * DD + c4 * 4);                                  \
            cp_async16(&Vs[(s) * 64 * VLD + r * VLD + c4 * 4],                         \
                       Vg + (size_t)r * DD + c4 * 4);                                  \
        }                                                                              \
    } while (0)

    ATT_LOAD_STAGE(0, 0);
    cp_commit();

    // ---- stage this warp's 32 Q rows into its slab; build 2 A-tiles ----
    float* Sw = Ss + (warp * 32) * KLD;   // warp slab: rows 0..31
    {
        const float* Qw = Qg + (size_t)(warp * 32) * DD;
#pragma unroll
        for (int i = lane; i < 32 * 16; i += 32) {
            int r = i >> 4, c4 = i & 15;
            *(float4*)&Sw[r * KLD + c4 * 4] = *(const float4*)(Qw + (size_t)r * DD + c4 * 4);
        }
    }
    __syncwarp();

    uint32_t aq0[8][4], aq1[8][4];
    {
        const float scale = 0.125f;   // exact power of two: tf32 stays tf32
        const int r0 = g * KLD, r1 = (g + 8) * KLD;
        const int r2 = (16 + g) * KLD, r3 = (24 + g) * KLD;
#pragma unroll
        for (int kk = 0; kk < 8; kk++) {
            aq0[kk][0] = __float_as_uint(Sw[r0 + 8 * kk + tg] * scale);
            aq0[kk][1] = __float_as_uint(Sw[r1 + 8 * kk + tg] * scale);
            aq0[kk][2] = __float_as_uint(Sw[r0 + 8 * kk + tg + 4] * scale);
            aq0[kk][3] = __float_as_uint(Sw[r1 + 8 * kk + tg + 4] * scale);
            aq1[kk][0] = __float_as_uint(Sw[r2 + 8 * kk + tg] * scale);
            aq1[kk][1] = __float_as_uint(Sw[r3 + 8 * kk + tg] * scale);
            aq1[kk][2] = __float_as_uint(Sw[r2 + 8 * kk + tg + 4] * scale);
            aq1[kk][3] = __float_as_uint(Sw[r3 + 8 * kk + tg + 4] * scale);
        }
    }
    __syncwarp();   // slab now free for P

    float o0[8][4], o1[8][4];
#pragma unroll
    for (int j = 0; j < 8; j++)
#pragma unroll
        for (int t = 0; t < 4; t++) { o0[j][t] = 0.f; o1[j][t] = 0.f; }
    float mA0 = -INFINITY, mB0 = -INFINITY, lA0 = 0.f, lB0 = 0.f;
    float mA1 = -INFINITY, mB1 = -INFINITY, lA1 = 0.f, lB1 = 0.f;

    cp_wait0();
    __syncthreads();

    for (int kt = 0; kt < SS / 64; kt++) {
        const int s = kt & 1;
        if (kt + 1 < SS / 64) { ATT_LOAD_STAGE(s ^ 1, kt + 1); cp_commit(); }

        const float* K = Ks + s * 64 * KLD;
        const float* V = Vs + s * 64 * VLD;

        // ---- S = (Q/8) K^T : 32 x 64 per warp, K fragment reused for 2 tiles ----
        float sc0[8][4], sc1[8][4];
#pragma unroll
        for (int j = 0; j < 8; j++)
#pragma unroll
            for (int t = 0; t < 4; t++) { sc0[j][t] = 0.f; sc1[j][t] = 0.f; }

#pragma unroll
        for (int kk = 0; kk < 8; kk++) {
#pragma unroll
            for (int j = 0; j < 8; j++) {
                uint32_t bfr[2];
                const int rn = (8 * j + g) * KLD + 8 * kk + tg;
                bfr[0] = __float_as_uint(K[rn]);
                bfr[1] = __float_as_uint(K[rn + 4]);
                mma_tf32(sc0[j], aq0[kk], bfr);
                mma_tf32(sc1[j], aq1[kk], bfr);
            }
        }

        // ---- online softmax in registers (4 rows per thread) ----
        float mxA0 = -INFINITY, mxB0 = -INFINITY, mxA1 = -INFINITY, mxB1 = -INFINITY;
#pragma unroll
        for (int j = 0; j < 8; j++) {
            mxA0 = fmaxf(mxA0, fmaxf(sc0[j][0], sc0[j][1]));
            mxB0 = fmaxf(mxB0, fmaxf(sc0[j][2], sc0[j][3]));
            mxA1 = fmaxf(mxA1, fmaxf(sc1[j][0], sc1[j][1]));
            mxB1 = fmaxf(mxB1, fmaxf(sc1[j][2], sc1[j][3]));
        }
#pragma unroll
        for (int off = 1; off <= 2; off <<= 1) {
            mxA0 = fmaxf(mxA0, __shfl_xor_sync(0xffffffffu, mxA0, off));
            mxB0 = fmaxf(mxB0, __shfl_xor_sync(0xffffffffu, mxB0, off));
            mxA1 = fmaxf(mxA1, __shfl_xor_sync(0xffffffffu, mxA1, off));
            mxB1 = fmaxf(mxB1, __shfl_xor_sync(0xffffffffu, mxB1, off));
        }

        const float mA0n = fmaxf(mA0, mxA0), mB0n = fmaxf(mB0, mxB0);
        const float mA1n = fmaxf(mA1, mxA1), mB1n = fmaxf(mB1, mxB1);
        const float aA0 = __expf(mA0 - mA0n), aB0 = __expf(mB0 - mB0n);
        const float aA1 = __expf(mA1 - mA1n), aB1 = __expf(mB1 - mB1n);

        float sA0 = 0.f, sB0 = 0.f, sA1 = 0.f, sB1 = 0.f;
#pragma unroll
        for (int j = 0; j < 8; j++) {
            sc0[j][0] = __expf(sc0[j][0] - mA0n);
            sc0[j][1] = __expf(sc0[j][1] - mA0n);
            sc0[j][2] = __expf(sc0[j][2] - mB0n);
            sc0[j][3] = __expf(sc0[j][3] - mB0n);
            sc1[j][0] = __expf(sc1[j][0] - mA1n);
            sc1[j][1] = __expf(sc1[j][1] - mA1n);
            sc1[j][2] = __expf(sc1[j][2] - mB1n);
            sc1[j][3] = __expf(sc1[j][3] - mB1n);
            sA0 += sc0[j][0] + sc0[j][1];
            sB0 += sc0[j][2] + sc0[j][3];
            sA1 += sc1[j][0] + sc1[j][1];
            sB1 += sc1[j][2] + sc1[j][3];
        }
#pragma unroll
        for (int off = 1; off <= 2; off <<= 1) {
            sA0 += __shfl_xor_sync(0xffffffffu, sA0, off);
            sB0 += __shfl_xor_sync(0xffffffffu, sB0, off);
            sA1 += __shfl_xor_sync(0xffffffffu, sA1, off);
            sB1 += __shfl_xor_sync(0xffffffffu, sB1, off);
        }

        lA0 = lA0 * aA0 + sA0;  mA0 = mA0n;
        lB0 = lB0 * aB0 + sB0;  mB0 = mB0n;
        lA1 = lA1 * aA1 + sA1;  mA1 = mA1n;
        lB1 = lB1 * aB1 + sB1;  mB1 = mB1n;

#pragma unroll
        for (int j = 0; j < 8; j++) {
            o0[j][0] *= aA0; o0[j][1] *= aA0; o0[j][2] *= aB0; o0[j][3] *= aB0;
            o1[j][0] *= aA1; o1[j][1] *= aA1; o1[j][2] *= aB1; o1[j][3] *= aB1;
        }

        // ---- P -> slab (pre-rounded tf32), then O += P V (V frag reused 2x) ----
#pragma unroll
        for (int j = 0; j < 8; j++) {
            *(float2*)&Sw[g * KLD + 8 * j + 2 * tg] =
                make_float2(__uint_as_float(f2tf32(sc0[j][0])),
                            __uint_as_float(f2tf32(sc0[j][1])));
            *(float2*)&Sw[(g + 8) * KLD + 8 * j + 2 * tg] =
                make_float2(__uint_as_float(f2tf32(sc0[j][2])),
                            __uint_as_float(f2tf32(sc0[j][3])));
            *(float2*)&Sw[(16 + g) * KLD + 8 * j + 2 * tg] =
                make_float2(__uint_as_float(f2tf32(sc1[j][0])),
                            __uint_as_float(f2tf32(sc1[j][1])));
            *(float2*)&Sw[(24 + g) * KLD + 8 * j + 2 * tg] =
                make_float2(__uint_as_float(f2tf32(sc1[j][2])),
                            __uint_as_float(f2tf32(sc1[j][3])));
        }
        __syncwarp();

#pragma unroll
        for (int kk = 0; kk < 8; kk++) {
            uint32_t pa0[4], pa1[4];
            pa0[0] = __float_as_uint(Sw[g * KLD + 8 * kk + tg]);
            pa0[1] = __float_as_uint(Sw[(g + 8) * KLD + 8 * kk + tg]);
            pa0[2] = __float_as_uint(Sw[g * KLD + 8 * kk + tg + 4]);
            pa0[3] = __float_as_uint(Sw[(g + 8) * KLD + 8 * kk + tg + 4]);
            pa1[0] = __float_as_uint(Sw[(16 + g) * KLD + 8 * kk + tg]);
            pa1[1] = __float_as_uint(Sw[(24 + g) * KLD + 8 * kk + tg]);
            pa1[2] = __float_as_uint(Sw[(16 + g) * KLD + 8 * kk + tg + 4]);
            pa1[3] = __float_as_uint(Sw[(24 + g) * KLD + 8 * kk + tg + 4]);
#pragma unroll
            for (int j = 0; j < 8; j++) {
                uint32_t bfr[2];
                const int rv = (8 * kk + tg) * VLD + 8 * j + g;
                bfr[0] = __float_as_uint(V[rv]);
                bfr[1] = __float_as_uint(V[rv + 4 * VLD]);
                mma_tf32(o0[j], pa0, bfr);
                mma_tf32(o1[j], pa1, bfr);
            }
        }

        cp_wait0();
        __syncthreads();   // guard K/V buffer reuse
    }

    // ---- epilogue: ctx = O / l, pre-rounded to tf32 for the final GEMM ----
    const float iA0 = 1.f / lA0, iB0 = 1.f / lB0;
    const float iA1 = 1.f / lA1, iB1 = 1.f / lB1;
    float* Cg = Ctx + (rowQ0 + warp * 32) * DD + colH;
#pragma unroll
    for (int j = 0; j < 8; j++) {
        const int col = 8 * j + 2 * tg;
        *(float2*)(Cg + (size_t)g * DD + col) =
            make_float2(__uint_as_float(f2tf32(o0[j][0] * iA0)),
                        __uint_as_float(f2tf32(o0[j][1] * iA0)));
        *(float2*)(Cg + (size_t)(g + 8) * DD + col) =
            make_float2(__uint_as_float(f2tf32(o0[j][2] * iB0)),
                        __uint_as_float(f2tf32(o0[j][3] * iB0)));
        *(float2*)(Cg + (size_t)(16 + g) * DD + col) =
            make_float2(__uint_as_float(f2tf32(o1[j][0] * iA1)),
                        __uint_as_float(f2tf32(o1[j][1] * iA1)));
        *(float2*)(Cg + (size_t)(24 + g) * DD + col) =
            make_float2(__uint_as_float(f2tf32(o1[j][2] * iB1)),
                        __uint_as_float(f2tf32(o1[j][3] * iB1)));
    }
#undef ATT_LOAD_STAGE
}

// ---------------- launch ------------------------------------------------------
extern "C" void kernel_launch(void* const* d_in, const int* /*in_sizes*/, int /*n_in*/,
                              void* d_out, int /*out_size*/)
{
    const float* q  = (const float*)d_in[0];
    const float* k  = (const float*)d_in[1];
    const float* v  = (const float*)d_in[2];
    const float* Wq = (const float*)d_in[3];
    const float* bq = (const float*)d_in[4];
    const float* Wk = (const float*)d_in[5];
    const float* bk = (const float*)d_in[6];
    const float* Wv = (const float*)d_in[7];
    const float* bv = (const float*)d_in[8];
    const float* Wo = (const float*)d_in[9];
    const float* bo = (const float*)d_in[10];
    float* out = (float*)d_out;

    float *Qh, *Kh, *Vh, *Ctx, *Xq, *Xk, *Xv, *Wqr, *Wkr, *Wvr, *Wor;
    cudaGetSymbolAddress((void**)&Qh,  g_Qh);
    cudaGetSymbolAddress((void**)&Kh,  g_Kh);
    cudaGetSymbolAddress((void**)&Vh,  g_Vh);
    cudaGetSymbolAddress((void**)&Ctx, g_Ctx);
    cudaGetSymbolAddress((void**)&Xq,  g_Xq);
    cudaGetSymbolAddress((void**)&Xk,  g_Xk);
    cudaGetSymbolAddress((void**)&Xv,  g_Xv);
    cudaGetSymbolAddress((void**)&Wqr, g_Wqr);
    cudaGetSymbolAddress((void**)&Wkr, g_Wkr);
    cudaGetSymbolAddress((void**)&Wvr, g_Wvr);
    cudaGetSymbolAddress((void**)&Wor, g_Wor);

    cudaFuncSetAttribute(gemm_bias_kernel<true>,
                         cudaFuncAttributeMaxDynamicSharedMemorySize, GEMM_SMEM_BYTES);
    cudaFuncSetAttribute(gemm_bias_kernel<false>,
                         cudaFuncAttributeMaxDynamicSharedMemorySize, GEMM_SMEM_BYTES);
    cudaFuncSetAttribute(attn_kernel,
                         cudaFuncAttributeMaxDynamicSharedMemorySize, ATT_SMEM_BYTES);

    // pre-round every GEMM operand to tf32 bits (cvt(cvt(x)) == cvt(x))
    const int rbX = (MM * DD / 4) / 256;   // 4096 blocks
    const int rbW = (DD * DD / 4) / 256;   // 1024 blocks
    round_tf32_kernel<<<rbX, 256>>>(q,  Xq);
    round_tf32_kernel<<<rbX, 256>>>(k,  Xk);
    round_tf32_kernel<<<rbX, 256>>>(v,  Xv);
    round_tf32_kernel<<<rbW, 256>>>(Wq, Wqr);
    round_tf32_kernel<<<rbW, 256>>>(Wk, Wkr);
    round_tf32_kernel<<<rbW, 256>>>(Wv, Wvr);
    round_tf32_kernel<<<rbW, 256>>>(Wo, Wor);

    const dim3 gg(DD / GBN, MM / GBM);   // (8, 32)

    // projections: outputs pre-rounded to tf32 for the attention kernel
    gemm_bias_kernel<true><<<gg, 256, GEMM_SMEM_BYTES>>>(Xq, Wqr, bq, Qh);
    gemm_bias_kernel<true><<<gg, 256, GEMM_SMEM_BYTES>>>(Xk, Wkr, bk, Kh);
    gemm_bias_kernel<true><<<gg, 256, GEMM_SMEM_BYTES>>>(Xv, Wvr, bv, Vh);

    attn_kernel<<<dim3(SS / 128, BB * HH), 128, ATT_SMEM_BYTES>>>(Qh, Kh, Vh, Ctx);

    // output projection: Ctx already tf32, full-precision store
    gemm_bias_kernel<false><<<gg, 256, GEMM_SMEM_BYTES>>>(Ctx, Wor, bo, out);
}

// round 9
// speedup vs baseline: 4.0871x; 1.1014x over previous
#include <cuda_runtime.h>
#include <cuda.h>
#include <math.h>
#include <stdint.h>

#define BB   2
#define SS   2048
#define DD   1024
#define HH   16
#define DKK  64
#define MM   (BB * SS)

__device__ float g_Qh[MM * DD];
__device__ float g_Kh[MM * DD];
__device__ float g_Vh[MM * DD];
__device__ float g_Ctx[MM * DD];
__device__ float g_Wqr[DD * DD];
__device__ float g_Wkr[DD * DD];
__device__ float g_Wvr[DD * DD];
__device__ float g_Wor[DD * DD];

// ---------------- PTX helpers --------------------------------------------------
__device__ __forceinline__ uint32_t f2tf32(float x) {
    uint32_t r; asm("cvt.rna.tf32.f32 %0, %1;\n" : "=r"(r) : "f"(x)); return r;
}
__device__ __forceinline__ float rndtf(float x) { return __uint_as_float(f2tf32(x)); }

__device__ __forceinline__ void mma_tf32(float c[4], const uint32_t a[4], const uint32_t b[2]) {
    asm volatile(
        "mma.sync.aligned.m16n8k8.row.col.f32.tf32.tf32.f32 "
        "{%0,%1,%2,%3}, {%4,%5,%6,%7}, {%8,%9}, {%0,%1,%2,%3};\n"
        : "+f"(c[0]), "+f"(c[1]), "+f"(c[2]), "+f"(c[3])
        : "r"(a[0]), "r"(a[1]), "r"(a[2]), "r"(a[3]), "r"(b[0]), "r"(b[1]));
}
__device__ __forceinline__ void cp_async16(void* smem, const void* gmem) {
    uint32_t s = (uint32_t)__cvta_generic_to_shared(smem);
    asm volatile("cp.async.cg.shared.global [%0], [%1], 16;\n" :: "r"(s), "l"(gmem));
}
__device__ __forceinline__ void cp_commit() { asm volatile("cp.async.commit_group;\n"); }
__device__ __forceinline__ void cp_wait0()  { asm volatile("cp.async.wait_group 0;\n"); }

__device__ __forceinline__ void mbar_init(uint32_t a, uint32_t cnt) {
    asm volatile("mbarrier.init.shared.b64 [%0], %1;" :: "r"(a), "r"(cnt) : "memory");
}
__device__ __forceinline__ void mbar_expect_tx(uint32_t a, uint32_t tx) {
    asm volatile("mbarrier.arrive.expect_tx.shared.b64 _, [%0], %1;" :: "r"(a), "r"(tx) : "memory");
}
__device__ __forceinline__ void mbar_wait(uint32_t a, int ph) {
    asm volatile(
        "{\n\t.reg .pred P;\n\t"
        "WL_%=:\n\t"
        "mbarrier.try_wait.parity.acquire.cta.shared::cta.b64 P, [%0], %1, 0x989680;\n\t"
        "@P bra.uni WD_%=;\n\t"
        "bra.uni WL_%=;\n\t"
        "WD_%=:\n\t}" :: "r"(a), "r"(ph) : "memory");
}
__device__ __forceinline__ void tma2d(uint32_t dst, const CUtensorMap* m, int cx, int cy,
                                      uint32_t mbar) {
    asm volatile(
        "cp.async.bulk.tensor.2d.shared::cta.global.tile.mbarrier::complete_tx::bytes "
        "[%0], [%1, {%2, %3}], [%4];"
        :: "r"(dst), "l"(m), "r"(cx), "r"(cy), "r"(mbar) : "memory");
}

// ---------------- batched tf32 pre-round of the 4 weight matrices ---------------
__global__ void round4_kernel(const float* __restrict__ a, const float* __restrict__ b,
                              const float* __restrict__ c, const float* __restrict__ d,
                              float* __restrict__ oa, float* __restrict__ ob,
                              float* __restrict__ oc, float* __restrict__ od)
{
    const float* s = (blockIdx.y == 0) ? a : (blockIdx.y == 1) ? b : (blockIdx.y == 2) ? c : d;
    float* o       = (blockIdx.y == 0) ? oa : (blockIdx.y == 1) ? ob : (blockIdx.y == 2) ? oc : od;
    const int i = blockIdx.x * blockDim.x + threadIdx.x;
    float4 v = ((const float4*)s)[i];
    v.x = rndtf(v.x); v.y = rndtf(v.y); v.z = rndtf(v.z); v.w = rndtf(v.w);
    ((float4*)o)[i] = v;
}

// ---------------- TMA GEMM: Y = X W^T + bias  (mma.sync compute) ----------------
// 128x128 CTA tile, K-chunks of 32 floats (one SW128 row), 2-stage TMA+mbarrier
// pipeline. Fragment loads apply the SW128 XOR: idx = r*32 + (c ^ ((r&7)*4));
// fragment rows satisfy r&7 == g, so the XOR term is g*4 (conflict-free).
// CVTA: cvt A-operand fp32->tf32 at fragment load (X is raw input).
// RND : round the output to tf32 bits for attention consumers.
#define TGA(s)   (1024u + (uint32_t)(s) * 32768u)
#define TGB(s)   (TGA(s) + 16384u)
#define TGBAR(s) (64u + (uint32_t)(s) * 8u)
#define TG_SMEM_BYTES (1024 + 2 * 32768)

template<bool CVTA, bool RND>
__global__ __launch_bounds__(256, 2) void gemm_tma_kernel(
    const __grid_constant__ CUtensorMap mapX,
    const __grid_constant__ CUtensorMap mapW,
    const float* __restrict__ bias, float* __restrict__ Y)
{
    extern __shared__ __align__(1024) char smem[];
    const uint32_t sb = (uint32_t)__cvta_generic_to_shared(smem);
    const int tid = threadIdx.x;
    const int warp = tid >> 5, lane = tid & 31;
    const int g = lane >> 2, tg = lane & 3;
    const int wm = warp >> 2, wn = warp & 3;
    const int m0 = blockIdx.y * 128, n0 = blockIdx.x * 128;
    const int xg = g * 4;   // SW128 XOR term for fragment rows

    if (tid == 0) { mbar_init(sb + TGBAR(0), 1); mbar_init(sb + TGBAR(1), 1); }
    __syncthreads();

    float c[4][4][4];
#pragma unroll
    for (int i = 0; i < 4; i++)
#pragma unroll
        for (int j = 0; j < 4; j++)
#pragma unroll
            for (int t = 0; t < 4; t++) c[i][j][t] = 0.f;

    if (tid == 0) {
        mbar_expect_tx(sb + TGBAR(0), 32768u);
        tma2d(sb + TGA(0), &mapX, 0, m0, sb + TGBAR(0));
        tma2d(sb + TGB(0), &mapW, 0, n0, sb + TGBAR(0));
    }

    int ph0 = 0, ph1 = 0;
    for (int kt = 0; kt < DD / 32; kt++) {
        const int s = kt & 1;
        if (kt + 1 < DD / 32 && tid == 0) {
            mbar_expect_tx(sb + TGBAR(s ^ 1), 32768u);
            tma2d(sb + TGA(s ^ 1), &mapX, (kt + 1) * 32, m0, sb + TGBAR(s ^ 1));
            tma2d(sb + TGB(s ^ 1), &mapW, (kt + 1) * 32, n0, sb + TGBAR(s ^ 1));
        }
        if (s == 0) { mbar_wait(sb + TGBAR(0), ph0); ph0 ^= 1; }
        else        { mbar_wait(sb + TGBAR(1), ph1); ph1 ^= 1; }

        const float* A = (const float*)(smem + TGA(s));
        const float* B = (const float*)(smem + TGB(s));
#pragma unroll
        for (int kk = 0; kk < 32; kk += 8) {
            const int c0 = (kk + tg) ^ xg;
            const int c1 = (kk + tg + 4) ^ xg;
            uint32_t a[4][4], b[4][2];
#pragma unroll
            for (int mi = 0; mi < 4; mi++) {
                const int rb = (wm * 64 + mi * 16 + g) * 32;
                if (CVTA) {
                    a[mi][0] = f2tf32(A[rb + c0]);
                    a[mi][1] = f2tf32(A[rb + 256 + c0]);
                    a[mi][2] = f2tf32(A[rb + c1]);
                    a[mi][3] = f2tf32(A[rb + 256 + c1]);
                } else {
                    a[mi][0] = __float_as_uint(A[rb + c0]);
                    a[mi][1] = __float_as_uint(A[rb + 256 + c0]);
                    a[mi][2] = __float_as_uint(A[rb + c1]);
                    a[mi][3] = __float_as_uint(A[rb + 256 + c1]);
                }
            }
#pragma unroll
            for (int nj = 0; nj < 4; nj++) {
                const int rb = (wn * 32 + nj * 8 + g) * 32;
                b[nj][0] = __float_as_uint(B[rb + c0]);
                b[nj][1] = __float_as_uint(B[rb + c1]);
            }
#pragma unroll
            for (int mi = 0; mi < 4; mi++)
#pragma unroll
                for (int nj = 0; nj < 4; nj++)
                    mma_tf32(c[mi][nj], a[mi], b[nj]);
        }
        __syncthreads();   // all reads of stage s done before it is refilled at kt+1
    }

    // epilogue: + bias, (RND), store
#pragma unroll
    for (int nj = 0; nj < 4; nj++) {
        const int coln = n0 + wn * 32 + nj * 8 + 2 * tg;
        const float2 bb = *(const float2*)(bias + coln);
#pragma unroll
        for (int mi = 0; mi < 4; mi++) {
            const int row = m0 + wm * 64 + mi * 16 + g;
            float y00 = c[mi][nj][0] + bb.x, y01 = c[mi][nj][1] + bb.y;
            float y10 = c[mi][nj][2] + bb.x, y11 = c[mi][nj][3] + bb.y;
            if (RND) { y00 = rndtf(y00); y01 = rndtf(y01); y10 = rndtf(y10); y11 = rndtf(y11); }
            *(float2*)(Y + (size_t)row * DD + coln)       = make_float2(y00, y01);
            *(float2*)(Y + (size_t)(row + 8) * DD + coln) = make_float2(y10, y11);
        }
    }
}

// ---------------- flash attention (R5 known-good, unchanged) --------------------
#define KLD 68
#define VLD 72
#define ATT_SMEM_BYTES ((2 * 64 * KLD + 2 * 64 * VLD + 128 * KLD) * 4)

__global__ __launch_bounds__(128, 2) void attn_kernel(
    const float* __restrict__ Qh, const float* __restrict__ Kh,
    const float* __restrict__ Vh, float* __restrict__ Ctx)
{
    extern __shared__ __align__(16) float sm[];
    float* Ks = sm;
    float* Vs = Ks + 2 * 64 * KLD;
    float* Ss = Vs + 2 * 64 * VLD;

    const int tid = threadIdx.x, warp = tid >> 5, lane = tid & 31;
    const int g = lane >> 2, tg = lane & 3;
    const int qt = blockIdx.x, bh = blockIdx.y;
    const int b = bh >> 4, h = bh & 15;

    const size_t rowQ0 = (size_t)(b * SS + qt * 128);
    const size_t colH  = (size_t)h * DKK;
    const float* Qg  = Qh + rowQ0 * DD + colH;
    const float* Kg0 = Kh + (size_t)(b * SS) * DD + colH;
    const float* Vg0 = Vh + (size_t)(b * SS) * DD + colH;

#define ATT_LOAD_STAGE(s, kt)                                                          \
    do {                                                                               \
        const float* Kg = Kg0 + (size_t)((kt) * 64) * DD;                              \
        const float* Vg = Vg0 + (size_t)((kt) * 64) * DD;                              \
        _Pragma("unroll")                                                              \
        for (int i = tid; i < 64 * 16; i += 128) {                                     \
            int r = i >> 4, c4 = i & 15;                                               \
            cp_async16(&Ks[(s) * 64 * KLD + r * KLD + c4 * 4],                         \
                       Kg + (size_t)r * DD + c4 * 4);                                  \
            cp_async16(&Vs[(s) * 64 * VLD + r * VLD + c4 * 4],                         \
                       Vg + (size_t)r * DD + c4 * 4);                                  \
        }                                                                              \
    } while (0)

    ATT_LOAD_STAGE(0, 0);
    cp_commit();

    float* Sw = Ss + (warp * 32) * KLD;
    {
        const float* Qw = Qg + (size_t)(warp * 32) * DD;
#pragma unroll
        for (int i = lane; i < 32 * 16; i += 32) {
            int r = i >> 4, c4 = i & 15;
            *(float4*)&Sw[r * KLD + c4 * 4] = *(const float4*)(Qw + (size_t)r * DD + c4 * 4);
        }
    }
    __syncwarp();

    uint32_t aq0[8][4], aq1[8][4];
    {
        const float scale = 0.125f;
        const int r0 = g * KLD, r1 = (g + 8) * KLD;
        const int r2 = (16 + g) * KLD, r3 = (24 + g) * KLD;
#pragma unroll
        for (int kk = 0; kk < 8; kk++) {
            aq0[kk][0] = __float_as_uint(Sw[r0 + 8 * kk + tg] * scale);
            aq0[kk][1] = __float_as_uint(Sw[r1 + 8 * kk + tg] * scale);
            aq0[kk][2] = __float_as_uint(Sw[r0 + 8 * kk + tg + 4] * scale);
            aq0[kk][3] = __float_as_uint(Sw[r1 + 8 * kk + tg + 4] * scale);
            aq1[kk][0] = __float_as_uint(Sw[r2 + 8 * kk + tg] * scale);
            aq1[kk][1] = __float_as_uint(Sw[r3 + 8 * kk + tg] * scale);
            aq1[kk][2] = __float_as_uint(Sw[r2 + 8 * kk + tg + 4] * scale);
            aq1[kk][3] = __float_as_uint(Sw[r3 + 8 * kk + tg + 4] * scale);
        }
    }
    __syncwarp();

    float o0[8][4], o1[8][4];
#pragma unroll
    for (int j = 0; j < 8; j++)
#pragma unroll
        for (int t = 0; t < 4; t++) { o0[j][t] = 0.f; o1[j][t] = 0.f; }
    float mA0 = -INFINITY, mB0 = -INFINITY, lA0 = 0.f, lB0 = 0.f;
    float mA1 = -INFINITY, mB1 = -INFINITY, lA1 = 0.f, lB1 = 0.f;

    cp_wait0();
    __syncthreads();

    for (int kt = 0; kt < SS / 64; kt++) {
        const int s = kt & 1;
        if (kt + 1 < SS / 64) { ATT_LOAD_STAGE(s ^ 1, kt + 1); cp_commit(); }

        const float* K = Ks + s * 64 * KLD;
        const float* V = Vs + s * 64 * VLD;

        float sc0[8][4], sc1[8][4];
#pragma unroll
        for (int j = 0; j < 8; j++)
#pragma unroll
            for (int t = 0; t < 4; t++) { sc0[j][t] = 0.f; sc1[j][t] = 0.f; }

#pragma unroll
        for (int kk = 0; kk < 8; kk++) {
#pragma unroll
            for (int j = 0; j < 8; j++) {
                uint32_t bfr[2];
                const int rn = (8 * j + g) * KLD + 8 * kk + tg;
                bfr[0] = __float_as_uint(K[rn]);
                bfr[1] = __float_as_uint(K[rn + 4]);
                mma_tf32(sc0[j], aq0[kk], bfr);
                mma_tf32(sc1[j], aq1[kk], bfr);
            }
        }

        float mxA0 = -INFINITY, mxB0 = -INFINITY, mxA1 = -INFINITY, mxB1 = -INFINITY;
#pragma unroll
        for (int j = 0; j < 8; j++) {
            mxA0 = fmaxf(mxA0, fmaxf(sc0[j][0], sc0[j][1]));
            mxB0 = fmaxf(mxB0, fmaxf(sc0[j][2], sc0[j][3]));
            mxA1 = fmaxf(mxA1, fmaxf(sc1[j][0], sc1[j][1]));
            mxB1 = fmaxf(mxB1, fmaxf(sc1[j][2], sc1[j][3]));
        }
#pragma unroll
        for (int off = 1; off <= 2; off <<= 1) {
            mxA0 = fmaxf(mxA0, __shfl_xor_sync(0xffffffffu, mxA0, off));
            mxB0 = fmaxf(mxB0, __shfl_xor_sync(0xffffffffu, mxB0, off));
            mxA1 = fmaxf(mxA1, __shfl_xor_sync(0xffffffffu, mxA1, off));
            mxB1 = fmaxf(mxB1, __shfl_xor_sync(0xffffffffu, mxB1, off));
        }

        const float mA0n = fmaxf(mA0, mxA0), mB0n = fmaxf(mB0, mxB0);
        const float mA1n = fmaxf(mA1, mxA1), mB1n = fmaxf(mB1, mxB1);
        const float aA0 = __expf(mA0 - mA0n), aB0 = __expf(mB0 - mB0n);
        const float aA1 = __expf(mA1 - mA1n), aB1 = __expf(mB1 - mB1n);

        float sA0 = 0.f, sB0 = 0.f, sA1 = 0.f, sB1 = 0.f;
#pragma unroll
        for (int j = 0; j < 8; j++) {
            sc0[j][0] = __expf(sc0[j][0] - mA0n);
            sc0[j][1] = __expf(sc0[j][1] - mA0n);
            sc0[j][2] = __expf(sc0[j][2] - mB0n);
            sc0[j][3] = __expf(sc0[j][3] - mB0n);
            sc1[j][0] = __expf(sc1[j][0] - mA1n);
            sc1[j][1] = __expf(sc1[j][1] - mA1n);
            sc1[j][2] = __expf(sc1[j][2] - mB1n);
            sc1[j][3] = __expf(sc1[j][3] - mB1n);
            sA0 += sc0[j][0] + sc0[j][1];
            sB0 += sc0[j][2] + sc0[j][3];
            sA1 += sc1[j][0] + sc1[j][1];
            sB1 += sc1[j][2] + sc1[j][3];
        }
#pragma unroll
        for (int off = 1; off <= 2; off <<= 1) {
            sA0 += __shfl_xor_sync(0xffffffffu, sA0, off);
            sB0 += __shfl_xor_sync(0xffffffffu, sB0, off);
            sA1 += __shfl_xor_sync(0xffffffffu, sA1, off);
            sB1 += __shfl_xor_sync(0xffffffffu, sB1, off);
        }

        lA0 = lA0 * aA0 + sA0;  mA0 = mA0n;
        lB0 = lB0 * aB0 + sB0;  mB0 = mB0n;
        lA1 = lA1 * aA1 + sA1;  mA1 = mA1n;
        lB1 = lB1 * aB1 + sB1;  mB1 = mB1n;

#pragma unroll
        for (int j = 0; j < 8; j++) {
            o0[j][0] *= aA0; o0[j][1] *= aA0; o0[j][2] *= aB0; o0[j][3] *= aB0;
            o1[j][0] *= aA1; o1[j][1] *= aA1; o1[j][2] *= aB1; o1[j][3] *= aB1;
        }

#pragma unroll
        for (int j = 0; j < 8; j++) {
            *(float2*)&Sw[g * KLD + 8 * j + 2 * tg] =
                make_float2(rndtf(sc0[j][0]), rndtf(sc0[j][1]));
            *(float2*)&Sw[(g + 8) * KLD + 8 * j + 2 * tg] =
                make_float2(rndtf(sc0[j][2]), rndtf(sc0[j][3]));
            *(float2*)&Sw[(16 + g) * KLD + 8 * j + 2 * tg] =
                make_float2(rndtf(sc1[j][0]), rndtf(sc1[j][1]));
            *(float2*)&Sw[(24 + g) * KLD + 8 * j + 2 * tg] =
                make_float2(rndtf(sc1[j][2]), rndtf(sc1[j][3]));
        }
        __syncwarp();

#pragma unroll
        for (int kk = 0; kk < 8; kk++) {
            uint32_t pa0[4], pa1[4];
            pa0[0] = __float_as_uint(Sw[g * KLD + 8 * kk + tg]);
            pa0[1] = __float_as_uint(Sw[(g + 8) * KLD + 8 * kk + tg]);
            pa0[2] = __float_as_uint(Sw[g * KLD + 8 * kk + tg + 4]);
            pa0[3] = __float_as_uint(Sw[(g + 8) * KLD + 8 * kk + tg + 4]);
            pa1[0] = __float_as_uint(Sw[(16 + g) * KLD + 8 * kk + tg]);
            pa1[1] = __float_as_uint(Sw[(24 + g) * KLD + 8 * kk + tg]);
            pa1[2] = __float_as_uint(Sw[(16 + g) * KLD + 8 * kk + tg + 4]);
            pa1[3] = __float_as_uint(Sw[(24 + g) * KLD + 8 * kk + tg + 4]);
#pragma unroll
            for (int j = 0; j < 8; j++) {
                uint32_t bfr[2];
                const int rv = (8 * kk + tg) * VLD + 8 * j + g;
                bfr[0] = __float_as_uint(V[rv]);
                bfr[1] = __float_as_uint(V[rv + 4 * VLD]);
                mma_tf32(o0[j], pa0, bfr);
                mma_tf32(o1[j], pa1, bfr);
            }
        }

        cp_wait0();
        __syncthreads();
    }

    const float iA0 = 1.f / lA0, iB0 = 1.f / lB0;
    const float iA1 = 1.f / lA1, iB1 = 1.f / lB1;
    float* Cg = Ctx + (rowQ0 + warp * 32) * DD + colH;
#pragma unroll
    for (int j = 0; j < 8; j++) {
        const int col = 8 * j + 2 * tg;
        *(float2*)(Cg + (size_t)g * DD + col) =
            make_float2(rndtf(o0[j][0] * iA0), rndtf(o0[j][1] * iA0));
        *(float2*)(Cg + (size_t)(g + 8) * DD + col) =
            make_float2(rndtf(o0[j][2] * iB0), rndtf(o0[j][3] * iB0));
        *(float2*)(Cg + (size_t)(16 + g) * DD + col) =
            make_float2(rndtf(o1[j][0] * iA1), rndtf(o1[j][1] * iA1));
        *(float2*)(Cg + (size_t)(24 + g) * DD + col) =
            make_float2(rndtf(o1[j][2] * iB1), rndtf(o1[j][3] * iB1));
    }
#undef ATT_LOAD_STAGE
}

// ---------------- host: tensor maps without -lcuda ------------------------------
typedef CUresult (*EncodeFn)(CUtensorMap*, CUtensorMapDataType, cuuint32_t, void*,
                             const cuuint64_t*, const cuuint64_t*, const cuuint32_t*,
                             const cuuint32_t*, CUtensorMapInterleave, CUtensorMapSwizzle,
                             CUtensorMapL2promotion, CUtensorMapFloatOOBfill);

static void make_map(EncodeFn enc, CUtensorMap* m, const float* ptr, uint64_t rows)
{
    cuuint64_t dims[2]    = {DD, rows};
    cuuint64_t strides[1] = {DD * sizeof(float)};
    cuuint32_t box[2]     = {32, 128};    // 32 fp32 = 128B = one SW128 row
    cuuint32_t es[2]      = {1, 1};
    enc(m, CU_TENSOR_MAP_DATA_TYPE_FLOAT32, 2, (void*)ptr, dims, strides, box, es,
        CU_TENSOR_MAP_INTERLEAVE_NONE, CU_TENSOR_MAP_SWIZZLE_128B,
        CU_TENSOR_MAP_L2_PROMOTION_L2_128B, CU_TENSOR_MAP_FLOAT_OOB_FILL_NONE);
}

extern "C" void kernel_launch(void* const* d_in, const int* /*in_sizes*/, int /*n_in*/,
                              void* d_out, int /*out_size*/)
{
    const float* q  = (const float*)d_in[0];
    const float* k  = (const float*)d_in[1];
    const float* v  = (const float*)d_in[2];
    const float* Wq = (const float*)d_in[3];
    const float* bq = (const float*)d_in[4];
    const float* Wk = (const float*)d_in[5];
    const float* bk = (const float*)d_in[6];
    const float* Wv = (const float*)d_in[7];
    const float* bv = (const float*)d_in[8];
    const float* Wo = (const float*)d_in[9];
    const float* bo = (const float*)d_in[10];
    float* out = (float*)d_out;

    float *Qh, *Kh, *Vh, *Ctx, *Wqr, *Wkr, *Wvr, *Wor;
    cudaGetSymbolAddress((void**)&Qh,  g_Qh);
    cudaGetSymbolAddress((void**)&Kh,  g_Kh);
    cudaGetSymbolAddress((void**)&Vh,  g_Vh);
    cudaGetSymbolAddress((void**)&Ctx, g_Ctx);
    cudaGetSymbolAddress((void**)&Wqr, g_Wqr);
    cudaGetSymbolAddress((void**)&Wkr, g_Wkr);
    cudaGetSymbolAddress((void**)&Wvr, g_Wvr);
    cudaGetSymbolAddress((void**)&Wor, g_Wor);

    static EncodeFn enc = nullptr;
    if (!enc) {
        void* p = nullptr;
        cudaDriverEntryPointQueryResult st;
        cudaGetDriverEntryPointByVersion("cuTensorMapEncodeTiled", &p, 12000,
                                         cudaEnableDefault, &st);
        enc = (EncodeFn)p;
    }
    CUtensorMap mXq, mXk, mXv, mWq, mWk, mWv, mWo, mCtx;
    make_map(enc, &mXq, q, MM);   make_map(enc, &mXk, k, MM);
    make_map(enc, &mXv, v, MM);   make_map(enc, &mCtx, Ctx, MM);
    make_map(enc, &mWq, Wqr, DD); make_map(enc, &mWk, Wkr, DD);
    make_map(enc, &mWv, Wvr, DD); make_map(enc, &mWo, Wor, DD);

    cudaFuncSetAttribute(gemm_tma_kernel<true, true>,
                         cudaFuncAttributeMaxDynamicSharedMemorySize, TG_SMEM_BYTES);
    cudaFuncSetAttribute(gemm_tma_kernel<false, false>,
                         cudaFuncAttributeMaxDynamicSharedMemorySize, TG_SMEM_BYTES);
    cudaFuncSetAttribute(attn_kernel,
                         cudaFuncAttributeMaxDynamicSharedMemorySize, ATT_SMEM_BYTES);

    // pre-round only the weights (X rounding fused into GEMM A-fragment cvts)
    round4_kernel<<<dim3((DD * DD / 4) / 256, 4), 256>>>(Wq, Wk, Wv, Wo, Wqr, Wkr, Wvr, Wor);

    const dim3 gg(DD / 128, MM / 128);   // (8, 32)
    gemm_tma_kernel<true, true><<<gg, 256, TG_SMEM_BYTES>>>(mXq, mWq, bq, Qh);
    gemm_tma_kernel<true, true><<<gg, 256, TG_SMEM_BYTES>>>(mXk, mWk, bk, Kh);
    gemm_tma_kernel<true, true><<<gg, 256, TG_SMEM_BYTES>>>(mXv, mWv, bv, Vh);

    attn_kernel<<<dim3(SS / 128, BB * HH), 128, ATT_SMEM_BYTES>>>(Qh, Kh, Vh, Ctx);

    gemm_tma_kernel<false, false><<<gg, 256, TG_SMEM_BYTES>>>(mCtx, mWo, bo, out);
}

// round 10
// speedup vs baseline: 4.1180x; 1.0075x over previous
#include <cuda_runtime.h>
#include <cuda.h>
#include <math.h>
#include <stdint.h>

#define BB   2
#define SS   2048
#define DD   1024
#define HH   16
#define DKK  64
#define MM   (BB * SS)

__device__ float g_Qh[MM * DD];
__device__ float g_Kh[MM * DD];
__device__ float g_Vh[MM * DD];
__device__ float g_Ctx[MM * DD];
__device__ float g_Wqr[DD * DD];
__device__ float g_Wkr[DD * DD];
__device__ float g_Wvr[DD * DD];
__device__ float g_Wor[DD * DD];

// ---------------- PTX helpers --------------------------------------------------
__device__ __forceinline__ uint32_t f2tf32(float x) {
    uint32_t r; asm("cvt.rna.tf32.f32 %0, %1;\n" : "=r"(r) : "f"(x)); return r;
}
__device__ __forceinline__ float rndtf(float x) { return __uint_as_float(f2tf32(x)); }

__device__ __forceinline__ void mma_tf32(float c[4], const uint32_t a[4], const uint32_t b[2]) {
    asm volatile(
        "mma.sync.aligned.m16n8k8.row.col.f32.tf32.tf32.f32 "
        "{%0,%1,%2,%3}, {%4,%5,%6,%7}, {%8,%9}, {%0,%1,%2,%3};\n"
        : "+f"(c[0]), "+f"(c[1]), "+f"(c[2]), "+f"(c[3])
        : "r"(a[0]), "r"(a[1]), "r"(a[2]), "r"(a[3]), "r"(b[0]), "r"(b[1]));
}
__device__ __forceinline__ void cp_async16(void* smem, const void* gmem) {
    uint32_t s = (uint32_t)__cvta_generic_to_shared(smem);
    asm volatile("cp.async.cg.shared.global [%0], [%1], 16;\n" :: "r"(s), "l"(gmem));
}
__device__ __forceinline__ void cp_commit() { asm volatile("cp.async.commit_group;\n"); }
__device__ __forceinline__ void cp_wait0()  { asm volatile("cp.async.wait_group 0;\n"); }

__device__ __forceinline__ void mbar_init(uint32_t a, uint32_t cnt) {
    asm volatile("mbarrier.init.shared.b64 [%0], %1;" :: "r"(a), "r"(cnt) : "memory");
}
__device__ __forceinline__ void mbar_expect_tx(uint32_t a, uint32_t tx) {
    asm volatile("mbarrier.arrive.expect_tx.shared.b64 _, [%0], %1;" :: "r"(a), "r"(tx) : "memory");
}
__device__ __forceinline__ void mbar_wait(uint32_t a, int ph) {
    asm volatile(
        "{\n\t.reg .pred P;\n\t"
        "WL_%=:\n\t"
        "mbarrier.try_wait.parity.acquire.cta.shared::cta.b64 P, [%0], %1, 0x989680;\n\t"
        "@P bra.uni WD_%=;\n\t"
        "bra.uni WL_%=;\n\t"
        "WD_%=:\n\t}" :: "r"(a), "r"(ph) : "memory");
}
__device__ __forceinline__ void tma2d(uint32_t dst, const CUtensorMap* m, int cx, int cy,
                                      uint32_t mbar) {
    asm volatile(
        "cp.async.bulk.tensor.2d.shared::cta.global.tile.mbarrier::complete_tx::bytes "
        "[%0], [%1, {%2, %3}], [%4];"
        :: "r"(dst), "l"(m), "r"(cx), "r"(cy), "r"(mbar) : "memory");
}

// ---------------- batched tf32 pre-round of the 4 weight matrices ---------------
__global__ void round4_kernel(const float* __restrict__ a, const float* __restrict__ b,
                              const float* __restrict__ c, const float* __restrict__ d,
                              float* __restrict__ oa, float* __restrict__ ob,
                              float* __restrict__ oc, float* __restrict__ od)
{
    const float* s = (blockIdx.y == 0) ? a : (blockIdx.y == 1) ? b : (blockIdx.y == 2) ? c : d;
    float* o       = (blockIdx.y == 0) ? oa : (blockIdx.y == 1) ? ob : (blockIdx.y == 2) ? oc : od;
    const int i = blockIdx.x * blockDim.x + threadIdx.x;
    float4 v = ((const float4*)s)[i];
    v.x = rndtf(v.x); v.y = rndtf(v.y); v.z = rndtf(v.z); v.w = rndtf(v.w);
    ((float4*)o)[i] = v;
}

// ---------------- TMA GEMM body: Y = X W^T + bias  (3-stage pipeline) -----------
// 128x128 CTA tile, K-chunks of 32 floats (one SW128 row). TMA for chunk t+3 is
// issued right after the sync retiring chunk t -> 2 iterations of slack.
// Fragment loads apply the SW128 XOR: idx = r*32 + (c ^ ((r&7)*4)); fragment rows
// satisfy r&7 == g so the XOR term is g*4 (conflict-free).
#define TGA(s)   (1024u + (uint32_t)(s) * 32768u)
#define TGB(s)   (TGA(s) + 16384u)
#define TGBAR(s) (64u + (uint32_t)(s) * 8u)
#define TG_SMEM_BYTES (1024 + 3 * 32768)
#define TG_NK (DD / 32)   // 32 chunks

template<bool CVTA, bool RND>
__device__ __forceinline__ void gemm_body(
    const CUtensorMap* mapX, const CUtensorMap* mapW,
    const float* __restrict__ bias, float* __restrict__ Y,
    char* smem, int m0, int n0)
{
    const uint32_t sb = (uint32_t)__cvta_generic_to_shared(smem);
    const int tid = threadIdx.x;
    const int warp = tid >> 5, lane = tid & 31;
    const int g = lane >> 2, tg = lane & 3;
    const int wm = warp >> 2, wn = warp & 3;
    const int xg = g * 4;

    if (tid == 0) {
#pragma unroll
        for (int s = 0; s < 3; s++) mbar_init(sb + TGBAR(s), 1);
    }
    __syncthreads();

    float c[4][4][4];
#pragma unroll
    for (int i = 0; i < 4; i++)
#pragma unroll
        for (int j = 0; j < 4; j++)
#pragma unroll
            for (int t = 0; t < 4; t++) c[i][j][t] = 0.f;

    if (tid == 0) {
#pragma unroll
        for (int cch = 0; cch < 3; cch++) {
            mbar_expect_tx(sb + TGBAR(cch), 32768u);
            tma2d(sb + TGA(cch), mapX, cch * 32, m0, sb + TGBAR(cch));
            tma2d(sb + TGB(cch), mapW, cch * 32, n0, sb + TGBAR(cch));
        }
    }

    int ph[3] = {0, 0, 0};
    for (int kt = 0; kt < TG_NK; kt++) {
        const int s = (kt % 3);
        mbar_wait(sb + TGBAR(s), ph[s]); ph[s] ^= 1;

        const float* A = (const float*)(smem + TGA(s));
        const float* B = (const float*)(smem + TGB(s));
#pragma unroll
        for (int kk = 0; kk < 32; kk += 8) {
            const int c0 = (kk + tg) ^ xg;
            const int c1 = (kk + tg + 4) ^ xg;
            uint32_t a[4][4], b[4][2];
#pragma unroll
            for (int mi = 0; mi < 4; mi++) {
                const int rb = (wm * 64 + mi * 16 + g) * 32;
                if (CVTA) {
                    a[mi][0] = f2tf32(A[rb + c0]);
                    a[mi][1] = f2tf32(A[rb + 256 + c0]);
                    a[mi][2] = f2tf32(A[rb + c1]);
                    a[mi][3] = f2tf32(A[rb + 256 + c1]);
                } else {
                    a[mi][0] = __float_as_uint(A[rb + c0]);
                    a[mi][1] = __float_as_uint(A[rb + 256 + c0]);
                    a[mi][2] = __float_as_uint(A[rb + c1]);
                    a[mi][3] = __float_as_uint(A[rb + 256 + c1]);
                }
            }
#pragma unroll
            for (int nj = 0; nj < 4; nj++) {
                const int rb = (wn * 32 + nj * 8 + g) * 32;
                b[nj][0] = __float_as_uint(B[rb + c0]);
                b[nj][1] = __float_as_uint(B[rb + c1]);
            }
#pragma unroll
            for (int mi = 0; mi < 4; mi++)
#pragma unroll
                for (int nj = 0; nj < 4; nj++)
                    mma_tf32(c[mi][nj], a[mi], b[nj]);
        }
        __syncthreads();   // stage s fully consumed by all warps
        if (kt + 3 < TG_NK && tid == 0) {
            mbar_expect_tx(sb + TGBAR(s), 32768u);
            tma2d(sb + TGA(s), mapX, (kt + 3) * 32, m0, sb + TGBAR(s));
            tma2d(sb + TGB(s), mapW, (kt + 3) * 32, n0, sb + TGBAR(s));
        }
    }

    // epilogue: + bias, (RND), store
#pragma unroll
    for (int nj = 0; nj < 4; nj++) {
        const int coln = n0 + wn * 32 + nj * 8 + 2 * tg;
        const float2 bb = *(const float2*)(bias + coln);
#pragma unroll
        for (int mi = 0; mi < 4; mi++) {
            const int row = m0 + wm * 64 + mi * 16 + g;
            float y00 = c[mi][nj][0] + bb.x, y01 = c[mi][nj][1] + bb.y;
            float y10 = c[mi][nj][2] + bb.x, y11 = c[mi][nj][3] + bb.y;
            if (RND) { y00 = rndtf(y00); y01 = rndtf(y01); y10 = rndtf(y10); y11 = rndtf(y11); }
            *(float2*)(Y + (size_t)row * DD + coln)       = make_float2(y00, y01);
            *(float2*)(Y + (size_t)(row + 8) * DD + coln) = make_float2(y10, y11);
        }
    }
}

// fused Q/K/V projection GEMMs: blockIdx.z selects the problem
__global__ __launch_bounds__(256, 2) void gemm3_kernel(
    const __grid_constant__ CUtensorMap mX0, const __grid_constant__ CUtensorMap mX1,
    const __grid_constant__ CUtensorMap mX2,
    const __grid_constant__ CUtensorMap mW0, const __grid_constant__ CUtensorMap mW1,
    const __grid_constant__ CUtensorMap mW2,
    const float* __restrict__ b0, const float* __restrict__ b1, const float* __restrict__ b2,
    float* __restrict__ y0, float* __restrict__ y1, float* __restrict__ y2)
{
    extern __shared__ __align__(1024) char smem[];
    const int z = blockIdx.z;
    const CUtensorMap* mapX = (z == 0) ? &mX0 : (z == 1) ? &mX1 : &mX2;
    const CUtensorMap* mapW = (z == 0) ? &mW0 : (z == 1) ? &mW1 : &mW2;
    const float* bias       = (z == 0) ? b0 : (z == 1) ? b1 : b2;
    float* Y                = (z == 0) ? y0 : (z == 1) ? y1 : y2;
    gemm_body<true, true>(mapX, mapW, bias, Y, smem,
                          blockIdx.y * 128, blockIdx.x * 128);
}

// single output-projection GEMM (Ctx is already tf32 bits)
__global__ __launch_bounds__(256, 2) void gemm1_kernel(
    const __grid_constant__ CUtensorMap mX, const __grid_constant__ CUtensorMap mW,
    const float* __restrict__ bias, float* __restrict__ Y)
{
    extern __shared__ __align__(1024) char smem[];
    gemm_body<false, false>(&mX, &mW, bias, Y, smem,
                            blockIdx.y * 128, blockIdx.x * 128);
}

// ---------------- flash attention (R5/R9 known-good, unchanged) -----------------
#define KLD 68
#define VLD 72
#define ATT_SMEM_BYTES ((2 * 64 * KLD + 2 * 64 * VLD + 128 * KLD) * 4)

__global__ __launch_bounds__(128, 2) void attn_kernel(
    const float* __restrict__ Qh, const float* __restrict__ Kh,
    const float* __restrict__ Vh, float* __restrict__ Ctx)
{
    extern __shared__ __align__(16) float sm[];
    float* Ks = sm;
    float* Vs = Ks + 2 * 64 * KLD;
    float* Ss = Vs + 2 * 64 * VLD;

    const int tid = threadIdx.x, warp = tid >> 5, lane = tid & 31;
    const int g = lane >> 2, tg = lane & 3;
    const int qt = blockIdx.x, bh = blockIdx.y;
    const int b = bh >> 4, h = bh & 15;

    const size_t rowQ0 = (size_t)(b * SS + qt * 128);
    const size_t colH  = (size_t)h * DKK;
    const float* Qg  = Qh + rowQ0 * DD + colH;
    const float* Kg0 = Kh + (size_t)(b * SS) * DD + colH;
    const float* Vg0 = Vh + (size_t)(b * SS) * DD + colH;

#define ATT_LOAD_STAGE(s, kt)                                                          \
    do {                                                                               \
        const float* Kg = Kg0 + (size_t)((kt) * 64) * DD;                              \
        const float* Vg = Vg0 + (size_t)((kt) * 64) * DD;                              \
        _Pragma("unroll")                                                              \
        for (int i = tid; i < 64 * 16; i += 128) {                                     \
            int r = i >> 4, c4 = i & 15;                                               \
            cp_async16(&Ks[(s) * 64 * KLD + r * KLD + c4 * 4],                         \
                       Kg + (size_t)r * DD + c4 * 4);                                  \
            cp_async16(&Vs[(s) * 64 * VLD + r * VLD + c4 * 4],                         \
                       Vg + (size_t)r * DD + c4 * 4);                                  \
        }                                                                              \
    } while (0)

    ATT_LOAD_STAGE(0, 0);
    cp_commit();

    float* Sw = Ss + (warp * 32) * KLD;
    {
        const float* Qw = Qg + (size_t)(warp * 32) * DD;
#pragma unroll
        for (int i = lane; i < 32 * 16; i += 32) {
            int r = i >> 4, c4 = i & 15;
            *(float4*)&Sw[r * KLD + c4 * 4] = *(const float4*)(Qw + (size_t)r * DD + c4 * 4);
        }
    }
    __syncwarp();

    uint32_t aq0[8][4], aq1[8][4];
    {
        const float scale = 0.125f;
        const int r0 = g * KLD, r1 = (g + 8) * KLD;
        const int r2 = (16 + g) * KLD, r3 = (24 + g) * KLD;
#pragma unroll
        for (int kk = 0; kk < 8; kk++) {
            aq0[kk][0] = __float_as_uint(Sw[r0 + 8 * kk + tg] * scale);
            aq0[kk][1] = __float_as_uint(Sw[r1 + 8 * kk + tg] * scale);
            aq0[kk][2] = __float_as_uint(Sw[r0 + 8 * kk + tg + 4] * scale);
            aq0[kk][3] = __float_as_uint(Sw[r1 + 8 * kk + tg + 4] * scale);
            aq1[kk][0] = __float_as_uint(Sw[r2 + 8 * kk + tg] * scale);
            aq1[kk][1] = __float_as_uint(Sw[r3 + 8 * kk + tg] * scale);
            aq1[kk][2] = __float_as_uint(Sw[r2 + 8 * kk + tg + 4] * scale);
            aq1[kk][3] = __float_as_uint(Sw[r3 + 8 * kk + tg + 4] * scale);
        }
    }
    __syncwarp();

    float o0[8][4], o1[8][4];
#pragma unroll
    for (int j = 0; j < 8; j++)
#pragma unroll
        for (int t = 0; t < 4; t++) { o0[j][t] = 0.f; o1[j][t] = 0.f; }
    float mA0 = -INFINITY, mB0 = -INFINITY, lA0 = 0.f, lB0 = 0.f;
    float mA1 = -INFINITY, mB1 = -INFINITY, lA1 = 0.f, lB1 = 0.f;

    cp_wait0();
    __syncthreads();

    for (int kt = 0; kt < SS / 64; kt++) {
        const int s = kt & 1;
        if (kt + 1 < SS / 64) { ATT_LOAD_STAGE(s ^ 1, kt + 1); cp_commit(); }

        const float* K = Ks + s * 64 * KLD;
        const float* V = Vs + s * 64 * VLD;

        float sc0[8][4], sc1[8][4];
#pragma unroll
        for (int j = 0; j < 8; j++)
#pragma unroll
            for (int t = 0; t < 4; t++) { sc0[j][t] = 0.f; sc1[j][t] = 0.f; }

#pragma unroll
        for (int kk = 0; kk < 8; kk++) {
#pragma unroll
            for (int j = 0; j < 8; j++) {
                uint32_t bfr[2];
                const int rn = (8 * j + g) * KLD + 8 * kk + tg;
                bfr[0] = __float_as_uint(K[rn]);
                bfr[1] = __float_as_uint(K[rn + 4]);
                mma_tf32(sc0[j], aq0[kk], bfr);
                mma_tf32(sc1[j], aq1[kk], bfr);
            }
        }

        float mxA0 = -INFINITY, mxB0 = -INFINITY, mxA1 = -INFINITY, mxB1 = -INFINITY;
#pragma unroll
        for (int j = 0; j < 8; j++) {
            mxA0 = fmaxf(mxA0, fmaxf(sc0[j][0], sc0[j][1]));
            mxB0 = fmaxf(mxB0, fmaxf(sc0[j][2], sc0[j][3]));
            mxA1 = fmaxf(mxA1, fmaxf(sc1[j][0], sc1[j][1]));
            mxB1 = fmaxf(mxB1, fmaxf(sc1[j][2], sc1[j][3]));
        }
#pragma unroll
        for (int off = 1; off <= 2; off <<= 1) {
            mxA0 = fmaxf(mxA0, __shfl_xor_sync(0xffffffffu, mxA0, off));
            mxB0 = fmaxf(mxB0, __shfl_xor_sync(0xffffffffu, mxB0, off));
            mxA1 = fmaxf(mxA1, __shfl_xor_sync(0xffffffffu, mxA1, off));
            mxB1 = fmaxf(mxB1, __shfl_xor_sync(0xffffffffu, mxB1, off));
        }

        const float mA0n = fmaxf(mA0, mxA0), mB0n = fmaxf(mB0, mxB0);
        const float mA1n = fmaxf(mA1, mxA1), mB1n = fmaxf(mB1, mxB1);
        const float aA0 = __expf(mA0 - mA0n), aB0 = __expf(mB0 - mB0n);
        const float aA1 = __expf(mA1 - mA1n), aB1 = __expf(mB1 - mB1n);

        float sA0 = 0.f, sB0 = 0.f, sA1 = 0.f, sB1 = 0.f;
#pragma unroll
        for (int j = 0; j < 8; j++) {
            sc0[j][0] = __expf(sc0[j][0] - mA0n);
            sc0[j][1] = __expf(sc0[j][1] - mA0n);
            sc0[j][2] = __expf(sc0[j][2] - mB0n);
            sc0[j][3] = __expf(sc0[j][3] - mB0n);
            sc1[j][0] = __expf(sc1[j][0] - mA1n);
            sc1[j][1] = __expf(sc1[j][1] - mA1n);
            sc1[j][2] = __expf(sc1[j][2] - mB1n);
            sc1[j][3] = __expf(sc1[j][3] - mB1n);
            sA0 += sc0[j][0] + sc0[j][1];
            sB0 += sc0[j][2] + sc0[j][3];
            sA1 += sc1[j][0] + sc1[j][1];
            sB1 += sc1[j][2] + sc1[j][3];
        }
#pragma unroll
        for (int off = 1; off <= 2; off <<= 1) {
            sA0 += __shfl_xor_sync(0xffffffffu, sA0, off);
            sB0 += __shfl_xor_sync(0xffffffffu, sB0, off);
            sA1 += __shfl_xor_sync(0xffffffffu, sA1, off);
            sB1 += __shfl_xor_sync(0xffffffffu, sB1, off);
        }

        lA0 = lA0 * aA0 + sA0;  mA0 = mA0n;
        lB0 = lB0 * aB0 + sB0;  mB0 = mB0n;
        lA1 = lA1 * aA1 + sA1;  mA1 = mA1n;
        lB1 = lB1 * aB1 + sB1;  mB1 = mB1n;

#pragma unroll
        for (int j = 0; j < 8; j++) {
            o0[j][0] *= aA0; o0[j][1] *= aA0; o0[j][2] *= aB0; o0[j][3] *= aB0;
            o1[j][0] *= aA1; o1[j][1] *= aA1; o1[j][2] *= aB1; o1[j][3] *= aB1;
        }

#pragma unroll
        for (int j = 0; j < 8; j++) {
            *(float2*)&Sw[g * KLD + 8 * j + 2 * tg] =
                make_float2(rndtf(sc0[j][0]), rndtf(sc0[j][1]));
            *(float2*)&Sw[(g + 8) * KLD + 8 * j + 2 * tg] =
                make_float2(rndtf(sc0[j][2]), rndtf(sc0[j][3]));
            *(float2*)&Sw[(16 + g) * KLD + 8 * j + 2 * tg] =
                make_float2(rndtf(sc1[j][0]), rndtf(sc1[j][1]));
            *(float2*)&Sw[(24 + g) * KLD + 8 * j + 2 * tg] =
                make_float2(rndtf(sc1[j][2]), rndtf(sc1[j][3]));
        }
        __syncwarp();

#pragma unroll
        for (int kk = 0; kk < 8; kk++) {
            uint32_t pa0[4], pa1[4];
            pa0[0] = __float_as_uint(Sw[g * KLD + 8 * kk + tg]);
            pa0[1] = __float_as_uint(Sw[(g + 8) * KLD + 8 * kk + tg]);
            pa0[2] = __float_as_uint(Sw[g * KLD + 8 * kk + tg + 4]);
            pa0[3] = __float_as_uint(Sw[(g + 8) * KLD + 8 * kk + tg + 4]);
            pa1[0] = __float_as_uint(Sw[(16 + g) * KLD + 8 * kk + tg]);
            pa1[1] = __float_as_uint(Sw[(24 + g) * KLD + 8 * kk + tg]);
            pa1[2] = __float_as_uint(Sw[(16 + g) * KLD + 8 * kk + tg + 4]);
            pa1[3] = __float_as_uint(Sw[(24 + g) * KLD + 8 * kk + tg + 4]);
#pragma unroll
            for (int j = 0; j < 8; j++) {
                uint32_t bfr[2];
                const int rv = (8 * kk + tg) * VLD + 8 * j + g;
                bfr[0] = __float_as_uint(V[rv]);
                bfr[1] = __float_as_uint(V[rv + 4 * VLD]);
                mma_tf32(o0[j], pa0, bfr);
                mma_tf32(o1[j], pa1, bfr);
            }
        }

        cp_wait0();
        __syncthreads();
    }

    const float iA0 = 1.f / lA0, iB0 = 1.f / lB0;
    const float iA1 = 1.f / lA1, iB1 = 1.f / lB1;
    float* Cg = Ctx + (rowQ0 + warp * 32) * DD + colH;
#pragma unroll
    for (int j = 0; j < 8; j++) {
        const int col = 8 * j + 2 * tg;
        *(float2*)(Cg + (size_t)g * DD + col) =
            make_float2(rndtf(o0[j][0] * iA0), rndtf(o0[j][1] * iA0));
        *(float2*)(Cg + (size_t)(g + 8) * DD + col) =
            make_float2(rndtf(o0[j][2] * iB0), rndtf(o0[j][3] * iB0));
        *(float2*)(Cg + (size_t)(16 + g) * DD + col) =
            make_float2(rndtf(o1[j][0] * iA1), rndtf(o1[j][1] * iA1));
        *(float2*)(Cg + (size_t)(24 + g) * DD + col) =
            make_float2(rndtf(o1[j][2] * iB1), rndtf(o1[j][3] * iB1));
    }
#undef ATT_LOAD_STAGE
}

// ---------------- host: tensor maps without -lcuda ------------------------------
typedef CUresult (*EncodeFn)(CUtensorMap*, CUtensorMapDataType, cuuint32_t, void*,
                             const cuuint64_t*, const cuuint64_t*, const cuuint32_t*,
                             const cuuint32_t*, CUtensorMapInterleave, CUtensorMapSwizzle,
                             CUtensorMapL2promotion, CUtensorMapFloatOOBfill);

static void make_map(EncodeFn enc, CUtensorMap* m, const float* ptr, uint64_t rows)
{
    cuuint64_t dims[2]    = {DD, rows};
    cuuint64_t strides[1] = {DD * sizeof(float)};
    cuuint32_t box[2]     = {32, 128};    // 32 fp32 = 128B = one SW128 row
    cuuint32_t es[2]      = {1, 1};
    enc(m, CU_TENSOR_MAP_DATA_TYPE_FLOAT32, 2, (void*)ptr, dims, strides, box, es,
        CU_TENSOR_MAP_INTERLEAVE_NONE, CU_TENSOR_MAP_SWIZZLE_128B,
        CU_TENSOR_MAP_L2_PROMOTION_L2_128B, CU_TENSOR_MAP_FLOAT_OOB_FILL_NONE);
}

extern "C" void kernel_launch(void* const* d_in, const int* /*in_sizes*/, int /*n_in*/,
                              void* d_out, int /*out_size*/)
{
    const float* q  = (const float*)d_in[0];
    const float* k  = (const float*)d_in[1];
    const float* v  = (const float*)d_in[2];
    const float* Wq = (const float*)d_in[3];
    const float* bq = (const float*)d_in[4];
    const float* Wk = (const float*)d_in[5];
    const float* bk = (const float*)d_in[6];
    const float* Wv = (const float*)d_in[7];
    const float* bv = (const float*)d_in[8];
    const float* Wo = (const float*)d_in[9];
    const float* bo = (const float*)d_in[10];
    float* out = (float*)d_out;

    float *Qh, *Kh, *Vh, *Ctx, *Wqr, *Wkr, *Wvr, *Wor;
    cudaGetSymbolAddress((void**)&Qh,  g_Qh);
    cudaGetSymbolAddress((void**)&Kh,  g_Kh);
    cudaGetSymbolAddress((void**)&Vh,  g_Vh);
    cudaGetSymbolAddress((void**)&Ctx, g_Ctx);
    cudaGetSymbolAddress((void**)&Wqr, g_Wqr);
    cudaGetSymbolAddress((void**)&Wkr, g_Wkr);
    cudaGetSymbolAddress((void**)&Wvr, g_Wvr);
    cudaGetSymbolAddress((void**)&Wor, g_Wor);

    static EncodeFn enc = nullptr;
    if (!enc) {
        void* p = nullptr;
        cudaDriverEntryPointQueryResult st;
        cudaGetDriverEntryPointByVersion("cuTensorMapEncodeTiled", &p, 12000,
                                         cudaEnableDefault, &st);
        enc = (EncodeFn)p;
    }
    CUtensorMap mXq, mXk, mXv, mWq, mWk, mWv, mWo, mCtx;
    make_map(enc, &mXq, q, MM);   make_map(enc, &mXk, k, MM);
    make_map(enc, &mXv, v, MM);   make_map(enc, &mCtx, Ctx, MM);
    make_map(enc, &mWq, Wqr, DD); make_map(enc, &mWk, Wkr, DD);
    make_map(enc, &mWv, Wvr, DD); make_map(enc, &mWo, Wor, DD);

    cudaFuncSetAttribute(gemm3_kernel,
                         cudaFuncAttributeMaxDynamicSharedMemorySize, TG_SMEM_BYTES);
    cudaFuncSetAttribute(gemm1_kernel,
                         cudaFuncAttributeMaxDynamicSharedMemorySize, TG_SMEM_BYTES);
    cudaFuncSetAttribute(attn_kernel,
                         cudaFuncAttributeMaxDynamicSharedMemorySize, ATT_SMEM_BYTES);

    // pre-round only the weights (X rounding fused into GEMM A-fragment cvts)
    round4_kernel<<<dim3((DD * DD / 4) / 256, 4), 256>>>(Wq, Wk, Wv, Wo, Wqr, Wkr, Wvr, Wor);

    // fused Q/K/V projections: one launch, 768 blocks
    gemm3_kernel<<<dim3(DD / 128, MM / 128, 3), 256, TG_SMEM_BYTES>>>(
        mXq, mXk, mXv, mWq, mWk, mWv, bq, bk, bv, Qh, Kh, Vh);

    attn_kernel<<<dim3(SS / 128, BB * HH), 128, ATT_SMEM_BYTES>>>(Qh, Kh, Vh, Ctx);

    gemm1_kernel<<<dim3(DD / 128, MM / 128), 256, TG_SMEM_BYTES>>>(mCtx, mWo, bo, out);
}

// round 12
// speedup vs baseline: 4.3692x; 1.0610x over previous
#include <cuda_runtime.h>
#include <cuda.h>
#include <math.h>
#include <stdint.h>

#define BB   2
#define SS   2048
#define DD   1024
#define HH   16
#define DKK  64
#define MM   (BB * SS)

__device__ float g_Qh[MM * DD];
__device__ float g_Kh[MM * DD];
__device__ float g_Vh[MM * DD];
__device__ float g_Ctx[MM * DD];
__device__ float g_Wqr[DD * DD];
__device__ float g_Wkr[DD * DD];
__device__ float g_Wvr[DD * DD];
__device__ float g_Wor[DD * DD];

// ---------------- PTX helpers --------------------------------------------------
__device__ __forceinline__ uint32_t f2tf32(float x) {
    uint32_t r; asm("cvt.rna.tf32.f32 %0, %1;\n" : "=r"(r) : "f"(x)); return r;
}
__device__ __forceinline__ float rndtf(float x) { return __uint_as_float(f2tf32(x)); }

__device__ __forceinline__ void mma_tf32(float c[4], const uint32_t a[4], const uint32_t b[2]) {
    asm volatile(
        "mma.sync.aligned.m16n8k8.row.col.f32.tf32.tf32.f32 "
        "{%0,%1,%2,%3}, {%4,%5,%6,%7}, {%8,%9}, {%0,%1,%2,%3};\n"
        : "+f"(c[0]), "+f"(c[1]), "+f"(c[2]), "+f"(c[3])
        : "r"(a[0]), "r"(a[1]), "r"(a[2]), "r"(a[3]), "r"(b[0]), "r"(b[1]));
}
__device__ __forceinline__ void cp_async16(void* smem, const void* gmem) {
    uint32_t s = (uint32_t)__cvta_generic_to_shared(smem);
    asm volatile("cp.async.cg.shared.global [%0], [%1], 16;\n" :: "r"(s), "l"(gmem));
}
__device__ __forceinline__ void cp_commit() { asm volatile("cp.async.commit_group;\n"); }
__device__ __forceinline__ void cp_wait0()  { asm volatile("cp.async.wait_group 0;\n"); }

__device__ __forceinline__ void mbar_init(uint32_t a, uint32_t cnt) {
    asm volatile("mbarrier.init.shared.b64 [%0], %1;" :: "r"(a), "r"(cnt) : "memory");
}
__device__ __forceinline__ void mbar_expect_tx(uint32_t a, uint32_t tx) {
    asm volatile("mbarrier.arrive.expect_tx.shared.b64 _, [%0], %1;" :: "r"(a), "r"(tx) : "memory");
}
__device__ __forceinline__ void mbar_wait(uint32_t a, int ph) {
    asm volatile(
        "{\n\t.reg .pred P;\n\t"
        "WL_%=:\n\t"
        "mbarrier.try_wait.parity.acquire.cta.shared::cta.b64 P, [%0], %1, 0x989680;\n\t"
        "@P bra.uni WD_%=;\n\t"
        "bra.uni WL_%=;\n\t"
        "WD_%=:\n\t}" :: "r"(a), "r"(ph) : "memory");
}
__device__ __forceinline__ void tma2d(uint32_t dst, const CUtensorMap* m, int cx, int cy,
                                      uint32_t mbar) {
    asm volatile(
        "cp.async.bulk.tensor.2d.shared::cta.global.tile.mbarrier::complete_tx::bytes "
        "[%0], [%1, {%2, %3}], [%4];"
        :: "r"(dst), "l"(m), "r"(cx), "r"(cy), "r"(mbar) : "memory");
}

// ---------------- batched tf32 pre-round of the 4 weight matrices ---------------
__global__ void round4_kernel(const float* __restrict__ a, const float* __restrict__ b,
                              const float* __restrict__ c, const float* __restrict__ d,
                              float* __restrict__ oa, float* __restrict__ ob,
                              float* __restrict__ oc, float* __restrict__ od)
{
    const float* s = (blockIdx.y == 0) ? a : (blockIdx.y == 1) ? b : (blockIdx.y == 2) ? c : d;
    float* o       = (blockIdx.y == 0) ? oa : (blockIdx.y == 1) ? ob : (blockIdx.y == 2) ? oc : od;
    const int i = blockIdx.x * blockDim.x + threadIdx.x;
    float4 v = ((const float4*)s)[i];
    v.x = rndtf(v.x); v.y = rndtf(v.y); v.z = rndtf(v.z); v.w = rndtf(v.w);
    ((float4*)o)[i] = v;
}

// ---------------- TMA GEMM body: Y = X W^T + bias  (warp tile 64x64) ------------
// 128x128 CTA tile, 128 threads (4 warps, 2x2), 3-stage TMA pipeline.
// Per kk: 32 LDS feed 32 mma (1.0 LDS/mma vs 1.5 before) -> tensor-bound.
// SW128 XOR on fragment loads: col ^ (g*4) since fragment rows have r&7 == g.
#define TGA(s)   (1024u + (uint32_t)(s) * 32768u)
#define TGB(s)   (TGA(s) + 16384u)
#define TGBAR(s) (64u + (uint32_t)(s) * 8u)
#define TG_SMEM_BYTES (1024 + 3 * 32768)
#define TG_NK (DD / 32)   // 32 chunks

template<bool CVTA, bool RND>
__device__ __forceinline__ void gemm_body(
    const CUtensorMap* mapX, const CUtensorMap* mapW,
    const float* __restrict__ bias, float* __restrict__ Y,
    char* smem, int m0, int n0)
{
    const uint32_t sb = (uint32_t)__cvta_generic_to_shared(smem);
    const int tid = threadIdx.x;
    const int warp = tid >> 5, lane = tid & 31;
    const int g = lane >> 2, tg = lane & 3;
    const int wm = warp >> 1, wn = warp & 1;   // 2x2 warps, 64x64 tiles
    const int xg = g * 4;

    if (tid == 0) {
#pragma unroll
        for (int s = 0; s < 3; s++) mbar_init(sb + TGBAR(s), 1);
    }
    __syncthreads();

    float c[4][8][4];
#pragma unroll
    for (int i = 0; i < 4; i++)
#pragma unroll
        for (int j = 0; j < 8; j++)
#pragma unroll
            for (int t = 0; t < 4; t++) c[i][j][t] = 0.f;

    if (tid == 0) {
#pragma unroll
        for (int cch = 0; cch < 3; cch++) {
            mbar_expect_tx(sb + TGBAR(cch), 32768u);
            tma2d(sb + TGA(cch), mapX, cch * 32, m0, sb + TGBAR(cch));
            tma2d(sb + TGB(cch), mapW, cch * 32, n0, sb + TGBAR(cch));
        }
    }

    int ph[3] = {0, 0, 0};
    for (int kt = 0; kt < TG_NK; kt++) {
        const int s = (kt % 3);
        mbar_wait(sb + TGBAR(s), ph[s]); ph[s] ^= 1;

        const float* A = (const float*)(smem + TGA(s));
        const float* B = (const float*)(smem + TGB(s));
#pragma unroll
        for (int kk = 0; kk < 32; kk += 8) {
            const int c0 = (kk + tg) ^ xg;
            const int c1 = (kk + tg + 4) ^ xg;
            uint32_t a[4][4], b[8][2];
#pragma unroll
            for (int mi = 0; mi < 4; mi++) {
                const int rb = (wm * 64 + mi * 16 + g) * 32;
                if (CVTA) {
                    a[mi][0] = f2tf32(A[rb + c0]);
                    a[mi][1] = f2tf32(A[rb + 256 + c0]);
                    a[mi][2] = f2tf32(A[rb + c1]);
                    a[mi][3] = f2tf32(A[rb + 256 + c1]);
                } else {
                    a[mi][0] = __float_as_uint(A[rb + c0]);
                    a[mi][1] = __float_as_uint(A[rb + 256 + c0]);
                    a[mi][2] = __float_as_uint(A[rb + c1]);
                    a[mi][3] = __float_as_uint(A[rb + 256 + c1]);
                }
            }
#pragma unroll
            for (int nj = 0; nj < 8; nj++) {
                const int rb = (wn * 64 + nj * 8 + g) * 32;
                b[nj][0] = __float_as_uint(B[rb + c0]);
                b[nj][1] = __float_as_uint(B[rb + c1]);
            }
#pragma unroll
            for (int mi = 0; mi < 4; mi++)
#pragma unroll
                for (int nj = 0; nj < 8; nj++)
                    mma_tf32(c[mi][nj], a[mi], b[nj]);
        }
        __syncthreads();   // stage s fully consumed by all warps
        if (kt + 3 < TG_NK && tid == 0) {
            mbar_expect_tx(sb + TGBAR(s), 32768u);
            tma2d(sb + TGA(s), mapX, (kt + 3) * 32, m0, sb + TGBAR(s));
            tma2d(sb + TGB(s), mapW, (kt + 3) * 32, n0, sb + TGBAR(s));
        }
    }

    // epilogue: + bias, (RND), store
#pragma unroll
    for (int nj = 0; nj < 8; nj++) {
        const int coln = n0 + wn * 64 + nj * 8 + 2 * tg;
        const float2 bb = *(const float2*)(bias + coln);
#pragma unroll
        for (int mi = 0; mi < 4; mi++) {
            const int row = m0 + wm * 64 + mi * 16 + g;
            float y00 = c[mi][nj][0] + bb.x, y01 = c[mi][nj][1] + bb.y;
            float y10 = c[mi][nj][2] + bb.x, y11 = c[mi][nj][3] + bb.y;
            if (RND) { y00 = rndtf(y00); y01 = rndtf(y01); y10 = rndtf(y10); y11 = rndtf(y11); }
            *(float2*)(Y + (size_t)row * DD + coln)       = make_float2(y00, y01);
            *(float2*)(Y + (size_t)(row + 8) * DD + coln) = make_float2(y10, y11);
        }
    }
}

// fused Q/K/V projection GEMMs: blockIdx.z selects the problem
__global__ __launch_bounds__(128, 2) void gemm3_kernel(
    const __grid_constant__ CUtensorMap mX0, const __grid_constant__ CUtensorMap mX1,
    const __grid_constant__ CUtensorMap mX2,
    const __grid_constant__ CUtensorMap mW0, const __grid_constant__ CUtensorMap mW1,
    const __grid_constant__ CUtensorMap mW2,
    const float* __restrict__ b0, const float* __restrict__ b1, const float* __restrict__ b2,
    float* __restrict__ y0, float* __restrict__ y1, float* __restrict__ y2)
{
    extern __shared__ __align__(1024) char smem[];
    const int z = blockIdx.z;
    const CUtensorMap* mapX = (z == 0) ? &mX0 : (z == 1) ? &mX1 : &mX2;
    const CUtensorMap* mapW = (z == 0) ? &mW0 : (z == 1) ? &mW1 : &mW2;
    const float* bias       = (z == 0) ? b0 : (z == 1) ? b1 : b2;
    float* Y                = (z == 0) ? y0 : (z == 1) ? y1 : y2;
    gemm_body<true, true>(mapX, mapW, bias, Y, smem,
                          blockIdx.y * 128, blockIdx.x * 128);
}

// single output-projection GEMM (Ctx is already tf32 bits)
__global__ __launch_bounds__(128, 2) void gemm1_kernel(
    const __grid_constant__ CUtensorMap mX, const __grid_constant__ CUtensorMap mW,
    const float* __restrict__ bias, float* __restrict__ Y)
{
    extern __shared__ __align__(1024) char smem[];
    gemm_body<false, false>(&mX, &mW, bias, Y, smem,
                            blockIdx.y * 128, blockIdx.x * 128);
}

// ---------------- flash attention (R5/R9 known-good, unchanged) -----------------
#define KLD 68
#define VLD 72
#define ATT_SMEM_BYTES ((2 * 64 * KLD + 2 * 64 * VLD + 128 * KLD) * 4)

__global__ __launch_bounds__(128, 2) void attn_kernel(
    const float* __restrict__ Qh, const float* __restrict__ Kh,
    const float* __restrict__ Vh, float* __restrict__ Ctx)
{
    extern __shared__ __align__(16) float sm[];
    float* Ks = sm;
    float* Vs = Ks + 2 * 64 * KLD;
    float* Ss = Vs + 2 * 64 * VLD;

    const int tid = threadIdx.x, warp = tid >> 5, lane = tid & 31;
    const int g = lane >> 2, tg = lane & 3;
    const int qt = blockIdx.x, bh = blockIdx.y;
    const int b = bh >> 4, h = bh & 15;

    const size_t rowQ0 = (size_t)(b * SS + qt * 128);
    const size_t colH  = (size_t)h * DKK;
    const float* Qg  = Qh + rowQ0 * DD + colH;
    const float* Kg0 = Kh + (size_t)(b * SS) * DD + colH;
    const float* Vg0 = Vh + (size_t)(b * SS) * DD + colH;

#define ATT_LOAD_STAGE(s, kt)                                                          \
    do {                                                                               \
        const float* Kg = Kg0 + (size_t)((kt) * 64) * DD;                              \
        const float* Vg = Vg0 + (size_t)((kt) * 64) * DD;                              \
        _Pragma("unroll")                                                              \
        for (int i = tid; i < 64 * 16; i += 128) {                                     \
            int r = i >> 4, c4 = i & 15;                                               \
            cp_async16(&Ks[(s) * 64 * KLD + r * KLD + c4 * 4],                         \
                       Kg + (size_t)r * DD + c4 * 4);                                  \
            cp_async16(&Vs[(s) * 64 * VLD + r * VLD + c4 * 4],                         \
                       Vg + (size_t)r * DD + c4 * 4);                                  \
        }                                                                              \
    } while (0)

    ATT_LOAD_STAGE(0, 0);
    cp_commit();

    float* Sw = Ss + (warp * 32) * KLD;
    {
        const float* Qw = Qg + (size_t)(warp * 32) * DD;
#pragma unroll
        for (int i = lane; i < 32 * 16; i += 32) {
            int r = i >> 4, c4 = i & 15;
            *(float4*)&Sw[r * KLD + c4 * 4] = *(const float4*)(Qw + (size_t)r * DD + c4 * 4);
        }
    }
    __syncwarp();

    uint32_t aq0[8][4], aq1[8][4];
    {
        const float scale = 0.125f;
        const int r0 = g * KLD, r1 = (g + 8) * KLD;
        const int r2 = (16 + g) * KLD, r3 = (24 + g) * KLD;
#pragma unroll
        for (int kk = 0; kk < 8; kk++) {
            aq0[kk][0] = __float_as_uint(Sw[r0 + 8 * kk + tg] * scale);
            aq0[kk][1] = __float_as_uint(Sw[r1 + 8 * kk + tg] * scale);
            aq0[kk][2] = __float_as_uint(Sw[r0 + 8 * kk + tg + 4] * scale);
            aq0[kk][3] = __float_as_uint(Sw[r1 + 8 * kk + tg + 4] * scale);
            aq1[kk][0] = __float_as_uint(Sw[r2 + 8 * kk + tg] * scale);
            aq1[kk][1] = __float_as_uint(Sw[r3 + 8 * kk + tg] * scale);
            aq1[kk][2] = __float_as_uint(Sw[r2 + 8 * kk + tg + 4] * scale);
            aq1[kk][3] = __float_as_uint(Sw[r3 + 8 * kk + tg + 4] * scale);
        }
    }
    __syncwarp();

    float o0[8][4], o1[8][4];
#pragma unroll
    for (int j = 0; j < 8; j++)
#pragma unroll
        for (int t = 0; t < 4; t++) { o0[j][t] = 0.f; o1[j][t] = 0.f; }
    float mA0 = -INFINITY, mB0 = -INFINITY, lA0 = 0.f, lB0 = 0.f;
    float mA1 = -INFINITY, mB1 = -INFINITY, lA1 = 0.f, lB1 = 0.f;

    cp_wait0();
    __syncthreads();

    for (int kt = 0; kt < SS / 64; kt++) {
        const int s = kt & 1;
        if (kt + 1 < SS / 64) { ATT_LOAD_STAGE(s ^ 1, kt + 1); cp_commit(); }

        const float* K = Ks + s * 64 * KLD;
        const float* V = Vs + s * 64 * VLD;

        float sc0[8][4], sc1[8][4];
#pragma unroll
        for (int j = 0; j < 8; j++)
#pragma unroll
            for (int t = 0; t < 4; t++) { sc0[j][t] = 0.f; sc1[j][t] = 0.f; }

#pragma unroll
        for (int kk = 0; kk < 8; kk++) {
#pragma unroll
            for (int j = 0; j < 8; j++) {
                uint32_t bfr[2];
                const int rn = (8 * j + g) * KLD + 8 * kk + tg;
                bfr[0] = __float_as_uint(K[rn]);
                bfr[1] = __float_as_uint(K[rn + 4]);
                mma_tf32(sc0[j], aq0[kk], bfr);
                mma_tf32(sc1[j], aq1[kk], bfr);
            }
        }

        float mxA0 = -INFINITY, mxB0 = -INFINITY, mxA1 = -INFINITY, mxB1 = -INFINITY;
#pragma unroll
        for (int j = 0; j < 8; j++) {
            mxA0 = fmaxf(mxA0, fmaxf(sc0[j][0], sc0[j][1]));
            mxB0 = fmaxf(mxB0, fmaxf(sc0[j][2], sc0[j][3]));
            mxA1 = fmaxf(mxA1, fmaxf(sc1[j][0], sc1[j][1]));
            mxB1 = fmaxf(mxB1, fmaxf(sc1[j][2], sc1[j][3]));
        }
#pragma unroll
        for (int off = 1; off <= 2; off <<= 1) {
            mxA0 = fmaxf(mxA0, __shfl_xor_sync(0xffffffffu, mxA0, off));
            mxB0 = fmaxf(mxB0, __shfl_xor_sync(0xffffffffu, mxB0, off));
            mxA1 = fmaxf(mxA1, __shfl_xor_sync(0xffffffffu, mxA1, off));
            mxB1 = fmaxf(mxB1, __shfl_xor_sync(0xffffffffu, mxB1, off));
        }

        const float mA0n = fmaxf(mA0, mxA0), mB0n = fmaxf(mB0, mxB0);
        const float mA1n = fmaxf(mA1, mxA1), mB1n = fmaxf(mB1, mxB1);
        const float aA0 = __expf(mA0 - mA0n), aB0 = __expf(mB0 - mB0n);
        const float aA1 = __expf(mA1 - mA1n), aB1 = __expf(mB1 - mB1n);

        float sA0 = 0.f, sB0 = 0.f, sA1 = 0.f, sB1 = 0.f;
#pragma unroll
        for (int j = 0; j < 8; j++) {
            sc0[j][0] = __expf(sc0[j][0] - mA0n);
            sc0[j][1] = __expf(sc0[j][1] - mA0n);
            sc0[j][2] = __expf(sc0[j][2] - mB0n);
            sc0[j][3] = __expf(sc0[j][3] - mB0n);
            sc1[j][0] = __expf(sc1[j][0] - mA1n);
            sc1[j][1] = __expf(sc1[j][1] - mA1n);
            sc1[j][2] = __expf(sc1[j][2] - mB1n);
            sc1[j][3] = __expf(sc1[j][3] - mB1n);
            sA0 += sc0[j][0] + sc0[j][1];
            sB0 += sc0[j][2] + sc0[j][3];
            sA1 += sc1[j][0] + sc1[j][1];
            sB1 += sc1[j][2] + sc1[j][3];
        }
#pragma unroll
        for (int off = 1; off <= 2; off <<= 1) {
            sA0 += __shfl_xor_sync(0xffffffffu, sA0, off);
            sB0 += __shfl_xor_sync(0xffffffffu, sB0, off);
            sA1 += __shfl_xor_sync(0xffffffffu, sA1, off);
            sB1 += __shfl_xor_sync(0xffffffffu, sB1, off);
        }

        lA0 = lA0 * aA0 + sA0;  mA0 = mA0n;
        lB0 = lB0 * aB0 + sB0;  mB0 = mB0n;
        lA1 = lA1 * aA1 + sA1;  mA1 = mA1n;
        lB1 = lB1 * aB1 + sB1;  mB1 = mB1n;

#pragma unroll
        for (int j = 0; j < 8; j++) {
            o0[j][0] *= aA0; o0[j][1] *= aA0; o0[j][2] *= aB0; o0[j][3] *= aB0;
            o1[j][0] *= aA1; o1[j][1] *= aA1; o1[j][2] *= aB1; o1[j][3] *= aB1;
        }

#pragma unroll
        for (int j = 0; j < 8; j++) {
            *(float2*)&Sw[g * KLD + 8 * j + 2 * tg] =
                make_float2(rndtf(sc0[j][0]), rndtf(sc0[j][1]));
            *(float2*)&Sw[(g + 8) * KLD + 8 * j + 2 * tg] =
                make_float2(rndtf(sc0[j][2]), rndtf(sc0[j][3]));
            *(float2*)&Sw[(16 + g) * KLD + 8 * j + 2 * tg] =
                make_float2(rndtf(sc1[j][0]), rndtf(sc1[j][1]));
            *(float2*)&Sw[(24 + g) * KLD + 8 * j + 2 * tg] =
                make_float2(rndtf(sc1[j][2]), rndtf(sc1[j][3]));
        }
        __syncwarp();

#pragma unroll
        for (int kk = 0; kk < 8; kk++) {
            uint32_t pa0[4], pa1[4];
            pa0[0] = __float_as_uint(Sw[g * KLD + 8 * kk + tg]);
            pa0[1] = __float_as_uint(Sw[(g + 8) * KLD + 8 * kk + tg]);
            pa0[2] = __float_as_uint(Sw[g * KLD + 8 * kk + tg + 4]);
            pa0[3] = __float_as_uint(Sw[(g + 8) * KLD + 8 * kk + tg + 4]);
            pa1[0] = __float_as_uint(Sw[(16 + g) * KLD + 8 * kk + tg]);
            pa1[1] = __float_as_uint(Sw[(24 + g) * KLD + 8 * kk + tg]);
            pa1[2] = __float_as_uint(Sw[(16 + g) * KLD + 8 * kk + tg + 4]);
            pa1[3] = __float_as_uint(Sw[(24 + g) * KLD + 8 * kk + tg + 4]);
#pragma unroll
            for (int j = 0; j < 8; j++) {
                uint32_t bfr[2];
                const int rv = (8 * kk + tg) * VLD + 8 * j + g;
                bfr[0] = __float_as_uint(V[rv]);
                bfr[1] = __float_as_uint(V[rv + 4 * VLD]);
                mma_tf32(o0[j], pa0, bfr);
                mma_tf32(o1[j], pa1, bfr);
            }
        }

        cp_wait0();
        __syncthreads();
    }

    const float iA0 = 1.f / lA0, iB0 = 1.f / lB0;
    const float iA1 = 1.f / lA1, iB1 = 1.f / lB1;
    float* Cg = Ctx + (rowQ0 + warp * 32) * DD + colH;
#pragma unroll
    for (int j = 0; j < 8; j++) {
        const int col = 8 * j + 2 * tg;
        *(float2*)(Cg + (size_t)g * DD + col) =
            make_float2(rndtf(o0[j][0] * iA0), rndtf(o0[j][1] * iA0));
        *(float2*)(Cg + (size_t)(g + 8) * DD + col) =
            make_float2(rndtf(o0[j][2] * iB0), rndtf(o0[j][3] * iB0));
        *(float2*)(Cg + (size_t)(16 + g) * DD + col) =
            make_float2(rndtf(o1[j][0] * iA1), rndtf(o1[j][1] * iA1));
        *(float2*)(Cg + (size_t)(24 + g) * DD + col) =
            make_float2(rndtf(o1[j][2] * iB1), rndtf(o1[j][3] * iB1));
    }
#undef ATT_LOAD_STAGE
}

// ---------------- host: tensor maps without -lcuda ------------------------------
typedef CUresult (*EncodeFn)(CUtensorMap*, CUtensorMapDataType, cuuint32_t, void*,
                             const cuuint64_t*, const cuuint64_t*, const cuuint32_t*,
                             const cuuint32_t*, CUtensorMapInterleave, CUtensorMapSwizzle,
                             CUtensorMapL2promotion, CUtensorMapFloatOOBfill);

static void make_map(EncodeFn enc, CUtensorMap* m, const float* ptr, uint64_t rows)
{
    cuuint64_t dims[2]    = {DD, rows};
    cuuint64_t strides[1] = {DD * sizeof(float)};
    cuuint32_t box[2]     = {32, 128};    // 32 fp32 = 128B = one SW128 row
    cuuint32_t es[2]      = {1, 1};
    enc(m, CU_TENSOR_MAP_DATA_TYPE_FLOAT32, 2, (void*)ptr, dims, strides, box, es,
        CU_TENSOR_MAP_INTERLEAVE_NONE, CU_TENSOR_MAP_SWIZZLE_128B,
        CU_TENSOR_MAP_L2_PROMOTION_L2_128B, CU_TENSOR_MAP_FLOAT_OOB_FILL_NONE);
}

extern "C" void kernel_launch(void* const* d_in, const int* /*in_sizes*/, int /*n_in*/,
                              void* d_out, int /*out_size*/)
{
    const float* q  = (const float*)d_in[0];
    const float* k  = (const float*)d_in[1];
    const float* v  = (const float*)d_in[2];
    const float* Wq = (const float*)d_in[3];
    const float* bq = (const float*)d_in[4];
    const float* Wk = (const float*)d_in[5];
    const float* bk = (const float*)d_in[6];
    const float* Wv = (const float*)d_in[7];
    const float* bv = (const float*)d_in[8];
    const float* Wo = (const float*)d_in[9];
    const float* bo = (const float*)d_in[10];
    float* out = (float*)d_out;

    float *Qh, *Kh, *Vh, *Ctx, *Wqr, *Wkr, *Wvr, *Wor;
    cudaGetSymbolAddress((void**)&Qh,  g_Qh);
    cudaGetSymbolAddress((void**)&Kh,  g_Kh);
    cudaGetSymbolAddress((void**)&Vh,  g_Vh);
    cudaGetSymbolAddress((void**)&Ctx, g_Ctx);
    cudaGetSymbolAddress((void**)&Wqr, g_Wqr);
    cudaGetSymbolAddress((void**)&Wkr, g_Wkr);
    cudaGetSymbolAddress((void**)&Wvr, g_Wvr);
    cudaGetSymbolAddress((void**)&Wor, g_Wor);

    static EncodeFn enc = nullptr;
    if (!enc) {
        void* p = nullptr;
        cudaDriverEntryPointQueryResult st;
        cudaGetDriverEntryPointByVersion("cuTensorMapEncodeTiled", &p, 12000,
                                         cudaEnableDefault, &st);
        enc = (EncodeFn)p;
    }
    CUtensorMap mXq, mXk, mXv, mWq, mWk, mWv, mWo, mCtx;
    make_map(enc, &mXq, q, MM);   make_map(enc, &mXk, k, MM);
    make_map(enc, &mXv, v, MM);   make_map(enc, &mCtx, Ctx, MM);
    make_map(enc, &mWq, Wqr, DD); make_map(enc, &mWk, Wkr, DD);
    make_map(enc, &mWv, Wvr, DD); make_map(enc, &mWo, Wor, DD);

    cudaFuncSetAttribute(gemm3_kernel,
                         cudaFuncAttributeMaxDynamicSharedMemorySize, TG_SMEM_BYTES);
    cudaFuncSetAttribute(gemm1_kernel,
                         cudaFuncAttributeMaxDynamicSharedMemorySize, TG_SMEM_BYTES);
    cudaFuncSetAttribute(attn_kernel,
                         cudaFuncAttributeMaxDynamicSharedMemorySize, ATT_SMEM_BYTES);

    // pre-round only the weights (X rounding fused into GEMM A-fragment cvts)
    round4_kernel<<<dim3((DD * DD / 4) / 256, 4), 256>>>(Wq, Wk, Wv, Wo, Wqr, Wkr, Wvr, Wor);

    // fused Q/K/V projections: one launch, 768 blocks of 128 threads
    gemm3_kernel<<<dim3(DD / 128, MM / 128, 3), 128, TG_SMEM_BYTES>>>(
        mXq, mXk, mXv, mWq, mWk, mWv, bq, bk, bv, Qh, Kh, Vh);

    attn_kernel<<<dim3(SS / 128, BB * HH), 128, ATT_SMEM_BYTES>>>(Qh, Kh, Vh, Ctx);

    gemm1_kernel<<<dim3(DD / 128, MM / 128), 128, TG_SMEM_BYTES>>>(mCtx, mWo, bo, out);
}